// round 1
// baseline (speedup 1.0000x reference)
#include <cuda_runtime.h>
#include <cuda_bf16.h>
#include <math.h>

// Problem constants
#define B_   1024
#define N_   24
#define L_   24
#define D_   128
#define V_   40000
#define VOUT 39999           // V-1 output columns
#define ALPHA_ 0.2f
#define NEG_ (-9e15f)

// ---------------- scratch (device globals; no runtime allocation) ----------------
static __device__ float g_Wc[384 * 128];        // folded fusion weight
static __device__ float g_bc[128];              // folded fusion bias
static __device__ float g_posw[24 * 128];       // pos_emb[::-1] @ w_1[:128]
static __device__ float g_h[B_ * N_ * D_];      // fused node features
static __device__ float g_hagg[B_ * N_ * D_];   // RGAT-aggregated features
static __device__ float g_select[B_ * D_];      // session representation

// ====================================================================
// Kernel 0: fold weights.
//  Wc[0:128]   = W_fuse[0:128]
//  Wc[128+k]   = sum_j W_img[k][j] * W_fuse[128+j]
//  Wc[256+k]   = sum_j W_txt[k][j] * W_fuse[256+j]
//  bc          = b_fuse + b_img@W_fuse[128:256] + b_txt@W_fuse[256:384]
//  g_posw[l]   = pos_emb[23-l] @ w_1[0:128]
// grid = 409 blocks x 128 threads
// ====================================================================
__global__ void k_precompute(const float* __restrict__ W_img, const float* __restrict__ b_img,
                             const float* __restrict__ W_txt, const float* __restrict__ b_txt,
                             const float* __restrict__ W_fuse, const float* __restrict__ b_fuse,
                             const float* __restrict__ pos_emb, const float* __restrict__ w_1) {
    int row = blockIdx.x;
    int d = threadIdx.x;
    if (row < 128) {
        g_Wc[row * 128 + d] = W_fuse[row * 128 + d];
    } else if (row < 256) {
        int k = row - 128;
        float s = 0.f;
        #pragma unroll 4
        for (int j = 0; j < 128; ++j) s += W_img[k * 128 + j] * W_fuse[(128 + j) * 128 + d];
        g_Wc[row * 128 + d] = s;
    } else if (row < 384) {
        int k = row - 256;
        float s = 0.f;
        #pragma unroll 4
        for (int j = 0; j < 128; ++j) s += W_txt[k * 128 + j] * W_fuse[(256 + j) * 128 + d];
        g_Wc[row * 128 + d] = s;
    } else if (row == 384) {
        float s = b_fuse[d];
        #pragma unroll 4
        for (int j = 0; j < 128; ++j) {
            s += b_img[j] * W_fuse[(128 + j) * 128 + d];
            s += b_txt[j] * W_fuse[(256 + j) * 128 + d];
        }
        g_bc[d] = s;
    } else {
        int l = row - 385;           // 0..23
        const float* pr = pos_emb + (size_t)(23 - l) * 128;
        float s = 0.f;
        #pragma unroll 4
        for (int k = 0; k < 128; ++k) s += pr[k] * w_1[k * 128 + d];
        g_posw[l * 128 + d] = s;
    }
}

// ====================================================================
// Kernel 1: fused multimodal embedding.
// h[row] = concat(emb[id], img_emb[id], txt_emb[id]) @ Wc + bc
// GEMM: M = B*N = 24576, K = 384, N = 128, with row gather.
// Block = 256 threads handles 32 rows; thread: d = tid&127, 16-row accum strip.
// ====================================================================
__global__ __launch_bounds__(256) void k_embed(const int* __restrict__ items,
                                               const float* __restrict__ emb,
                                               const float* __restrict__ img_emb,
                                               const float* __restrict__ txt_emb) {
    __shared__ float Ash[32][129];
    __shared__ int ids[32];
    int rowbase = blockIdx.x * 32;
    int tid = threadIdx.x;
    int d = tid & 127;
    int rh = tid >> 7;               // 0 or 1
    int r0 = rh * 16;

    if (tid < 32) ids[tid] = items[rowbase + tid];

    float acc[16];
    #pragma unroll
    for (int i = 0; i < 16; ++i) acc[i] = 0.f;

    for (int c = 0; c < 3; ++c) {
        __syncthreads();
        const float* src = (c == 0) ? emb : (c == 1) ? img_emb : txt_emb;
        for (int idx = tid; idx < 32 * 128; idx += 256) {
            int r = idx >> 7, cc = idx & 127;
            Ash[r][cc] = src[(size_t)ids[r] * 128 + cc];
        }
        __syncthreads();
        const float* wc = g_Wc + (size_t)c * 128 * 128 + d;
        #pragma unroll 4
        for (int k = 0; k < 128; ++k) {
            float w = wc[(size_t)k * 128];
            #pragma unroll
            for (int rr = 0; rr < 16; ++rr) acc[rr] += Ash[r0 + rr][k] * w;
        }
    }
    float bias = g_bc[d];
    #pragma unroll
    for (int rr = 0; rr < 16; ++rr)
        g_h[(size_t)(rowbase + r0 + rr) * 128 + d] = acc[rr] + bias;
}

// ====================================================================
// Kernel 2: RGAT layer. One block per batch (1024 blocks, 256 threads).
// e[i][j] = leaky( sum_d h_i[d]*h_j[d]*a_rel[adj-1][d] ), adj==0 -> NEG
// att = softmax_j, h_agg = att @ h
// ====================================================================
__global__ __launch_bounds__(256) void k_rgat(const int* __restrict__ adj,
                                              const float* __restrict__ a_rel) {
    __shared__ float hsh[24][129];
    __shared__ float esh[24][24];
    __shared__ float arel[4][128];
    int b = blockIdx.x;
    int tid = threadIdx.x;

    for (int idx = tid; idx < 24 * 128; idx += 256)
        hsh[idx >> 7][idx & 127] = g_h[(size_t)b * (24 * 128) + idx];
    for (int idx = tid; idx < 4 * 128; idx += 256)
        arel[idx >> 7][idx & 127] = a_rel[idx];
    __syncthreads();

    for (int p = tid; p < 576; p += 256) {
        int i = p / 24, j = p % 24;
        int a = adj[b * 576 + p];
        float v;
        if (a == 0) {
            v = NEG_;
        } else {
            const float* ar = arel[a - 1];
            float s = 0.f;
            #pragma unroll 4
            for (int d2 = 0; d2 < 128; ++d2) s += hsh[i][d2] * hsh[j][d2] * ar[d2];
            v = (s > 0.f) ? s : ALPHA_ * s;
        }
        esh[i][j] = v;
    }
    __syncthreads();

    if (tid < 24) {
        float mx = -INFINITY;
        #pragma unroll
        for (int j = 0; j < 24; ++j) mx = fmaxf(mx, esh[tid][j]);
        float sum = 0.f;
        #pragma unroll
        for (int j = 0; j < 24; ++j) {
            float e = expf(esh[tid][j] - mx);
            esh[tid][j] = e;
            sum += e;
        }
        float inv = 1.f / sum;
        #pragma unroll
        for (int j = 0; j < 24; ++j) esh[tid][j] *= inv;
    }
    __syncthreads();

    for (int idx = tid; idx < 24 * 128; idx += 256) {
        int i = idx >> 7, d2 = idx & 127;
        float s = 0.f;
        #pragma unroll
        for (int j = 0; j < 24; ++j) s += esh[i][j] * hsh[j][d2];
        g_hagg[(size_t)b * (24 * 128) + idx] = s;
    }
}

// ====================================================================
// Kernel 3: session readout. One block per batch (1024 blocks, 128 threads).
// hs = masked mean(seq); nh = tanh(posw + seq@w_1[128:]); gate = sigmoid(nh@glu1 + b + hs@glu2)
// beta = gate@w_2; select = sum_l beta*seq*m
// ====================================================================
__global__ __launch_bounds__(128) void k_readout(const int* __restrict__ alias_,
                                                 const int* __restrict__ mask_,
                                                 const float* __restrict__ w_1,
                                                 const float* __restrict__ w_2,
                                                 const float* __restrict__ glu1_w,
                                                 const float* __restrict__ glu1_b,
                                                 const float* __restrict__ glu2_w) {
    __shared__ float seq[24][128];
    __shared__ float hssh[128];
    __shared__ float nhsh[128];
    __shared__ int al[24];
    __shared__ float mk[24];
    __shared__ float red[4];
    int b = blockIdx.x;
    int d = threadIdx.x;

    if (d < 24) {
        al[d] = alias_[b * 24 + d];
        mk[d] = (float)mask_[b * 24 + d];
    }
    __syncthreads();
    for (int idx = d; idx < 24 * 128; idx += 128) {
        int l = idx >> 7, dd = idx & 127;
        seq[l][dd] = g_hagg[((size_t)b * 24 + al[l]) * 128 + dd];
    }
    __syncthreads();

    float msum = 0.f, hs = 0.f;
    #pragma unroll
    for (int l = 0; l < 24; ++l) { msum += mk[l]; hs += mk[l] * seq[l][d]; }
    hs /= fmaxf(msum, 1.f);
    hssh[d] = hs;
    __syncthreads();

    float hsg = 0.f;
    #pragma unroll 4
    for (int k = 0; k < 128; ++k) hsg += hssh[k] * glu2_w[k * 128 + d];
    float g1b = glu1_b[d];
    float w2d = w_2[d];

    float sel = 0.f;
    for (int l = 0; l < 24; ++l) {
        float s = g_posw[l * 128 + d];
        #pragma unroll 4
        for (int k = 0; k < 128; ++k) s += seq[l][k] * w_1[(128 + k) * 128 + d];
        float nh = tanhf(s);
        nhsh[d] = nh;
        __syncthreads();

        float g = g1b + hsg;
        #pragma unroll 4
        for (int k = 0; k < 128; ++k) g += nhsh[k] * glu1_w[k * 128 + d];
        g = 1.f / (1.f + expf(-g));

        float part = g * w2d;
        #pragma unroll
        for (int off = 16; off > 0; off >>= 1)
            part += __shfl_down_sync(0xffffffffu, part, off);
        if ((d & 31) == 0) red[d >> 5] = part;
        __syncthreads();
        float beta = red[0] + red[1] + red[2] + red[3];
        sel += beta * seq[l][d] * mk[l];
        __syncthreads();   // protect nhsh/red for next l
    }
    g_select[b * 128 + d] = sel;
}

// ====================================================================
// Kernel 4: scores = select @ emb[1:].T   -> out [1024, 39999]
// Tile: BM=128, BN=64, 256 threads, per-thread 8x4 register tile.
// Dynamic smem: A[128][129] + B[64][129] floats = 99072 bytes.
// ====================================================================
#define LDT 129
__global__ __launch_bounds__(256) void k_scores(const float* __restrict__ emb,
                                                float* __restrict__ out) {
    extern __shared__ float smem[];
    float* Ash = smem;                 // [128][LDT]
    float* Bsh = smem + 128 * LDT;     // [64][LDT]

    int v0 = blockIdx.x * 64;
    int m0 = blockIdx.y * 128;
    int tid = threadIdx.x;

    for (int idx = tid; idx < 128 * 128; idx += 256) {
        int m = idx >> 7, k = idx & 127;
        Ash[m * LDT + k] = g_select[(size_t)(m0 + m) * 128 + k];
    }
    for (int idx = tid; idx < 64 * 128; idx += 256) {
        int n = idx >> 7, k = idx & 127;
        int v = v0 + n;
        Bsh[n * LDT + k] = (v < VOUT) ? emb[(size_t)(v + 1) * 128 + k] : 0.f;
    }
    __syncthreads();

    int tx = tid & 15;   // n group
    int ty = tid >> 4;   // m group
    int mt = ty * 8;
    int nt = tx * 4;

    float acc[8][4];
    #pragma unroll
    for (int i = 0; i < 8; ++i)
        #pragma unroll
        for (int j = 0; j < 4; ++j) acc[i][j] = 0.f;

    #pragma unroll 8
    for (int k = 0; k < 128; ++k) {
        float bv[4];
        #pragma unroll
        for (int j = 0; j < 4; ++j) bv[j] = Bsh[(nt + j) * LDT + k];
        #pragma unroll
        for (int i = 0; i < 8; ++i) {
            float av = Ash[(mt + i) * LDT + k];
            #pragma unroll
            for (int j = 0; j < 4; ++j) acc[i][j] += av * bv[j];
        }
    }

    #pragma unroll
    for (int i = 0; i < 8; ++i) {
        int gm = m0 + mt + i;
        float* orow = out + (size_t)gm * VOUT + v0 + nt;
        #pragma unroll
        for (int j = 0; j < 4; ++j) {
            int gv = v0 + nt + j;
            if (gv < VOUT) orow[j] = acc[i][j];
        }
    }
}

// ====================================================================
// launch
// ====================================================================
extern "C" void kernel_launch(void* const* d_in, const int* in_sizes, int n_in,
                              void* d_out, int out_size) {
    const int*   items   = (const int*)d_in[0];
    const int*   adj     = (const int*)d_in[1];
    const int*   alias_  = (const int*)d_in[2];
    const int*   mask_   = (const int*)d_in[3];
    const float* emb     = (const float*)d_in[4];
    const float* img_emb = (const float*)d_in[5];
    const float* txt_emb = (const float*)d_in[6];
    const float* W_img   = (const float*)d_in[7];
    const float* b_img   = (const float*)d_in[8];
    const float* W_txt   = (const float*)d_in[9];
    const float* b_txt   = (const float*)d_in[10];
    const float* W_fuse  = (const float*)d_in[11];
    const float* b_fuse  = (const float*)d_in[12];
    const float* a_rel   = (const float*)d_in[13];
    const float* pos_emb = (const float*)d_in[14];
    const float* w_1     = (const float*)d_in[15];
    const float* w_2     = (const float*)d_in[16];
    const float* glu1_w  = (const float*)d_in[17];
    const float* glu1_b  = (const float*)d_in[18];
    const float* glu2_w  = (const float*)d_in[19];
    float* out = (float*)d_out;

    // 0: fold weights + pos projection
    k_precompute<<<409, 128>>>(W_img, b_img, W_txt, b_txt, W_fuse, b_fuse, pos_emb, w_1);

    // 1: fused embedding GEMM (24576 rows, 32 per block)
    k_embed<<<(B_ * N_) / 32, 256>>>(items, emb, img_emb, txt_emb);

    // 2: RGAT per batch
    k_rgat<<<B_, 256>>>(adj, a_rel);

    // 3: readout per batch
    k_readout<<<B_, 128>>>(alias_, mask_, w_1, w_2, glu1_w, glu1_b, glu2_w);

    // 4: scoring GEMM
    static int smem_set = 0;
    int smem_bytes = (128 + 64) * LDT * (int)sizeof(float);  // 99072
    if (!smem_set) {
        cudaFuncSetAttribute(k_scores, cudaFuncAttributeMaxDynamicSharedMemorySize, smem_bytes);
        smem_set = 1;
    }
    dim3 grid((VOUT + 63) / 64, B_ / 128);
    k_scores<<<grid, 256, smem_bytes>>>(emb, out);
}

// round 4
// speedup vs baseline: 1.2369x; 1.2369x over previous
#include <cuda_runtime.h>
#include <cuda_bf16.h>
#include <math.h>

// Problem constants
#define B_   1024
#define N_   24
#define L_   24
#define D_   128
#define V_   40000
#define VOUT 39999           // V-1 output columns
#define ALPHA_ 0.2f
#define NEG_ (-9e15f)

// ---------------- scratch (device globals; no runtime allocation) ----------------
static __device__ float g_Wc[384 * 128];        // folded fusion weight
static __device__ float g_bc[128];              // folded fusion bias
static __device__ float g_posw[24 * 128];       // pos_emb[::-1] @ w_1[:128]
static __device__ float g_h[B_ * N_ * D_];      // fused node features
static __device__ float g_hagg[B_ * N_ * D_];   // RGAT-aggregated features
static __device__ float g_select[B_ * D_];      // session representation

// ====================================================================
// Kernel 0: fold weights + pos projection (unchanged)
// ====================================================================
__global__ void k_precompute(const float* __restrict__ W_img, const float* __restrict__ b_img,
                             const float* __restrict__ W_txt, const float* __restrict__ b_txt,
                             const float* __restrict__ W_fuse, const float* __restrict__ b_fuse,
                             const float* __restrict__ pos_emb, const float* __restrict__ w_1) {
    int row = blockIdx.x;
    int d = threadIdx.x;
    if (row < 128) {
        g_Wc[row * 128 + d] = W_fuse[row * 128 + d];
    } else if (row < 256) {
        int k = row - 128;
        float s = 0.f;
        #pragma unroll 4
        for (int j = 0; j < 128; ++j) s += W_img[k * 128 + j] * W_fuse[(128 + j) * 128 + d];
        g_Wc[row * 128 + d] = s;
    } else if (row < 384) {
        int k = row - 256;
        float s = 0.f;
        #pragma unroll 4
        for (int j = 0; j < 128; ++j) s += W_txt[k * 128 + j] * W_fuse[(256 + j) * 128 + d];
        g_Wc[row * 128 + d] = s;
    } else if (row == 384) {
        float s = b_fuse[d];
        #pragma unroll 4
        for (int j = 0; j < 128; ++j) {
            s += b_img[j] * W_fuse[(128 + j) * 128 + d];
            s += b_txt[j] * W_fuse[(256 + j) * 128 + d];
        }
        g_bc[d] = s;
    } else {
        int l = row - 385;           // 0..23
        const float* pr = pos_emb + (size_t)(23 - l) * 128;
        float s = 0.f;
        #pragma unroll 4
        for (int k = 0; k < 128; ++k) s += pr[k] * w_1[k * 128 + d];
        g_posw[l * 128 + d] = s;
    }
}

// ====================================================================
// Kernel 1: fused multimodal embedding (float4-vectorized smem reads).
// ====================================================================
__global__ __launch_bounds__(256) void k_embed(const int* __restrict__ items,
                                               const float* __restrict__ emb,
                                               const float* __restrict__ img_emb,
                                               const float* __restrict__ txt_emb) {
    __shared__ __align__(16) float Ash[32][132];   // 132%4==0 -> float4-aligned rows
    __shared__ int ids[32];
    int rowbase = blockIdx.x * 32;
    int tid = threadIdx.x;
    int d = tid & 127;
    int rh = tid >> 7;               // 0 or 1
    int r0 = rh * 16;

    if (tid < 32) ids[tid] = items[rowbase + tid];

    float acc[16];
    #pragma unroll
    for (int i = 0; i < 16; ++i) acc[i] = 0.f;

    for (int c = 0; c < 3; ++c) {
        __syncthreads();
        const float* src = (c == 0) ? emb : (c == 1) ? img_emb : txt_emb;
        for (int idx = tid; idx < 32 * 128; idx += 256) {
            int r = idx >> 7, cc = idx & 127;
            Ash[r][cc] = src[(size_t)ids[r] * 128 + cc];
        }
        __syncthreads();
        const float* wc = g_Wc + (size_t)c * 128 * 128 + d;
        #pragma unroll 4
        for (int k = 0; k < 128; k += 4) {
            float w0 = wc[(size_t)(k + 0) * 128];
            float w1 = wc[(size_t)(k + 1) * 128];
            float w2 = wc[(size_t)(k + 2) * 128];
            float w3 = wc[(size_t)(k + 3) * 128];
            #pragma unroll
            for (int rr = 0; rr < 16; ++rr) {
                float4 s4 = *(const float4*)&Ash[r0 + rr][k];
                acc[rr] += s4.x * w0 + s4.y * w1 + s4.z * w2 + s4.w * w3;
            }
        }
    }
    float bias = g_bc[d];
    #pragma unroll
    for (int rr = 0; rr < 16; ++rr)
        g_h[(size_t)(rowbase + r0 + rr) * 128 + d] = acc[rr] + bias;
}

// ====================================================================
// Kernel 2: RGAT layer (float4-vectorized e-computation).
// ====================================================================
__global__ __launch_bounds__(256) void k_rgat(const int* __restrict__ adj,
                                              const float* __restrict__ a_rel) {
    __shared__ __align__(16) float hsh[24][128];
    __shared__ float esh[24][24];
    __shared__ __align__(16) float arel[4][128];
    int b = blockIdx.x;
    int tid = threadIdx.x;

    for (int idx = tid; idx < 24 * 128; idx += 256)
        hsh[idx >> 7][idx & 127] = g_h[(size_t)b * (24 * 128) + idx];
    for (int idx = tid; idx < 4 * 128; idx += 256)
        arel[idx >> 7][idx & 127] = a_rel[idx];
    __syncthreads();

    for (int p = tid; p < 576; p += 256) {
        int i = p / 24, j = p % 24;
        int a = adj[b * 576 + p];
        float v;
        if (a == 0) {
            v = NEG_;
        } else {
            const float* ar = arel[a - 1];
            float s = 0.f;
            #pragma unroll 8
            for (int d2 = 0; d2 < 128; d2 += 4) {
                float4 hi = *(const float4*)&hsh[i][d2];
                float4 hj = *(const float4*)&hsh[j][d2];
                float4 aa = *(const float4*)&ar[d2];
                s += hi.x * hj.x * aa.x + hi.y * hj.y * aa.y
                   + hi.z * hj.z * aa.z + hi.w * hj.w * aa.w;
            }
            v = (s > 0.f) ? s : ALPHA_ * s;
        }
        esh[i][j] = v;
    }
    __syncthreads();

    if (tid < 24) {
        float mx = -INFINITY;
        #pragma unroll
        for (int j = 0; j < 24; ++j) mx = fmaxf(mx, esh[tid][j]);
        float sum = 0.f;
        #pragma unroll
        for (int j = 0; j < 24; ++j) {
            float e = expf(esh[tid][j] - mx);
            esh[tid][j] = e;
            sum += e;
        }
        float inv = 1.f / sum;
        #pragma unroll
        for (int j = 0; j < 24; ++j) esh[tid][j] *= inv;
    }
    __syncthreads();

    for (int idx = tid; idx < 24 * 128; idx += 256) {
        int i = idx >> 7, d2 = idx & 127;
        float s = 0.f;
        #pragma unroll
        for (int j = 0; j < 24; ++j) s += esh[i][j] * hsh[j][d2];
        g_hagg[(size_t)b * (24 * 128) + idx] = s;
    }
}

// ====================================================================
// Kernel 3: session readout — k-outer register-tiled (the R1 fix).
// Each block (1 batch, 128 threads): thread owns column d, holds all 24
// l-accumulators in registers; each weight matrix is swept ONCE.
// ====================================================================
__global__ __launch_bounds__(128) void k_readout(const int* __restrict__ alias_,
                                                 const int* __restrict__ mask_,
                                                 const float* __restrict__ w_1,
                                                 const float* __restrict__ w_2,
                                                 const float* __restrict__ glu1_w,
                                                 const float* __restrict__ glu1_b,
                                                 const float* __restrict__ glu2_w) {
    __shared__ __align__(16) float seq[24][128];
    __shared__ __align__(16) float nhsh[24][128];
    __shared__ float hssh[128];
    __shared__ int al[24];
    __shared__ float mk[24];
    __shared__ float betash[24];
    int b = blockIdx.x;
    int d = threadIdx.x;

    if (d < 24) {
        al[d] = alias_[b * 24 + d];
        mk[d] = (float)mask_[b * 24 + d];
    }
    __syncthreads();
    #pragma unroll
    for (int l = 0; l < 24; ++l)
        seq[l][d] = g_hagg[((size_t)b * 24 + al[l]) * 128 + d];
    __syncthreads();

    // masked mean hs
    float msum = 0.f, hs = 0.f;
    #pragma unroll
    for (int l = 0; l < 24; ++l) { msum += mk[l]; hs += mk[l] * seq[l][d]; }
    hs /= fmaxf(msum, 1.f);
    hssh[d] = hs;
    __syncthreads();

    // hsg[d] = hs @ glu2_w (column d)
    float hsg = 0.f;
    #pragma unroll 4
    for (int k = 0; k < 128; ++k) hsg += hssh[k] * glu2_w[k * 128 + d];

    // --- nh = tanh(posw + seq @ w_1[128:256]) : k-outer, weights read once ---
    float acc[24];
    #pragma unroll
    for (int l = 0; l < 24; ++l) acc[l] = g_posw[l * 128 + d];

    #pragma unroll 2
    for (int k = 0; k < 128; k += 4) {
        float w0 = w_1[(128 + k + 0) * 128 + d];
        float w1 = w_1[(128 + k + 1) * 128 + d];
        float w2c = w_1[(128 + k + 2) * 128 + d];
        float w3 = w_1[(128 + k + 3) * 128 + d];
        #pragma unroll
        for (int l = 0; l < 24; ++l) {
            float4 s4 = *(const float4*)&seq[l][k];   // broadcast
            acc[l] += s4.x * w0 + s4.y * w1 + s4.z * w2c + s4.w * w3;
        }
    }
    #pragma unroll
    for (int l = 0; l < 24; ++l) nhsh[l][d] = tanhf(acc[l]);
    __syncthreads();

    // --- gate = sigmoid(nh @ glu1_w + glu1_b + hsg) ---
    float base = glu1_b[d] + hsg;
    #pragma unroll
    for (int l = 0; l < 24; ++l) acc[l] = base;

    #pragma unroll 2
    for (int k = 0; k < 128; k += 4) {
        float w0 = glu1_w[(k + 0) * 128 + d];
        float w1 = glu1_w[(k + 1) * 128 + d];
        float w2c = glu1_w[(k + 2) * 128 + d];
        float w3 = glu1_w[(k + 3) * 128 + d];
        #pragma unroll
        for (int l = 0; l < 24; ++l) {
            float4 s4 = *(const float4*)&nhsh[l][k];  // broadcast
            acc[l] += s4.x * w0 + s4.y * w1 + s4.z * w2c + s4.w * w3;
        }
    }
    float w2d = w_2[d];
    __syncthreads();   // everyone done reading nhsh before overwrite
    #pragma unroll
    for (int l = 0; l < 24; ++l)
        nhsh[l][d] = (1.f / (1.f + expf(-acc[l]))) * w2d;   // gate*w2 contribution
    __syncthreads();

    // beta[l] = sum_d gate[l][d]*w2[d], masked
    if (d < 24) {
        float s = 0.f;
        #pragma unroll 8
        for (int k = 0; k < 128; k += 4) {
            float4 p4 = *(const float4*)&nhsh[d][k];
            s += p4.x + p4.y + p4.z + p4.w;
        }
        betash[d] = s * mk[d];
    }
    __syncthreads();

    float sel = 0.f;
    #pragma unroll
    for (int l = 0; l < 24; ++l) sel += betash[l] * seq[l][d];
    g_select[b * 128 + d] = sel;
}

// ====================================================================
// Kernel 4: scores = select @ emb[1:].T  -> out [1024, 39999]
// 128x128 tile, K=128 fully resident, k-major smem (transposed on load,
// conflict-free), 256 threads x 8x8 register tile.
// smem = 2 * 128 * 129 * 4 = 132096 bytes (1 block/SM).
// ====================================================================
#define LDA 129
#define LDB 129
__global__ __launch_bounds__(256) void k_scores(const float* __restrict__ emb,
                                                float* __restrict__ out) {
    extern __shared__ float smem[];
    float* Ash = smem;                 // [k][m]: Ash[k*LDA + m]
    float* Bsh = smem + 128 * LDA;     // [k][n]: Bsh[k*LDB + n]

    int v0 = blockIdx.x * 128;
    int m0 = blockIdx.y * 128;
    int tid = threadIdx.x;

    // load + transpose A (coalesced LDG over k; STS banks = (k + m) % 32, conflict-free)
    for (int idx = tid; idx < 128 * 128; idx += 256) {
        int m = idx >> 7, k = idx & 127;
        Ash[k * LDA + m] = g_select[(size_t)(m0 + m) * 128 + k];
    }
    // load + transpose B
    for (int idx = tid; idx < 128 * 128; idx += 256) {
        int n = idx >> 7, k = idx & 127;
        int v = v0 + n;
        Bsh[k * LDB + n] = (v < VOUT) ? emb[(size_t)(v + 1) * 128 + k] : 0.f;
    }
    __syncthreads();

    int tx = tid & 15;   // n lane: columns tx + 16*j (strided, conflict-free LDS)
    int ty = tid >> 4;   // m group: rows ty*8 + i
    int mt = ty * 8;

    float acc[8][8];
    #pragma unroll
    for (int i = 0; i < 8; ++i)
        #pragma unroll
        for (int j = 0; j < 8; ++j) acc[i][j] = 0.f;

    #pragma unroll 8
    for (int k = 0; k < 128; ++k) {
        float a[8], bv[8];
        #pragma unroll
        for (int i = 0; i < 8; ++i) a[i] = Ash[k * LDA + mt + i];
        #pragma unroll
        for (int j = 0; j < 8; ++j) bv[j] = Bsh[k * LDB + tx + j * 16];
        #pragma unroll
        for (int i = 0; i < 8; ++i)
            #pragma unroll
            for (int j = 0; j < 8; ++j) acc[i][j] += a[i] * bv[j];
    }

    #pragma unroll
    for (int i = 0; i < 8; ++i) {
        int gm = m0 + mt + i;
        float* orow = out + (size_t)gm * VOUT;
        #pragma unroll
        for (int j = 0; j < 8; ++j) {
            int gv = v0 + tx + j * 16;
            if (gv < VOUT) orow[gv] = acc[i][j];
        }
    }
}

// ====================================================================
// launch
// ====================================================================
extern "C" void kernel_launch(void* const* d_in, const int* in_sizes, int n_in,
                              void* d_out, int out_size) {
    const int*   items   = (const int*)d_in[0];
    const int*   adj     = (const int*)d_in[1];
    const int*   alias_  = (const int*)d_in[2];
    const int*   mask_   = (const int*)d_in[3];
    const float* emb     = (const float*)d_in[4];
    const float* img_emb = (const float*)d_in[5];
    const float* txt_emb = (const float*)d_in[6];
    const float* W_img   = (const float*)d_in[7];
    const float* b_img   = (const float*)d_in[8];
    const float* W_txt   = (const float*)d_in[9];
    const float* b_txt   = (const float*)d_in[10];
    const float* W_fuse  = (const float*)d_in[11];
    const float* b_fuse  = (const float*)d_in[12];
    const float* a_rel   = (const float*)d_in[13];
    const float* pos_emb = (const float*)d_in[14];
    const float* w_1     = (const float*)d_in[15];
    const float* w_2     = (const float*)d_in[16];
    const float* glu1_w  = (const float*)d_in[17];
    const float* glu1_b  = (const float*)d_in[18];
    const float* glu2_w  = (const float*)d_in[19];
    float* out = (float*)d_out;

    // 0: fold weights + pos projection
    k_precompute<<<409, 128>>>(W_img, b_img, W_txt, b_txt, W_fuse, b_fuse, pos_emb, w_1);

    // 1: fused embedding GEMM
    k_embed<<<(B_ * N_) / 32, 256>>>(items, emb, img_emb, txt_emb);

    // 2: RGAT per batch
    k_rgat<<<B_, 256>>>(adj, a_rel);

    // 3: readout per batch (k-outer register GEMM)
    k_readout<<<B_, 128>>>(alias_, mask_, w_1, w_2, glu1_w, glu1_b, glu2_w);

    // 4: scoring GEMM
    int smem_bytes = 2 * 128 * LDA * (int)sizeof(float);  // 132096
    cudaFuncSetAttribute(k_scores, cudaFuncAttributeMaxDynamicSharedMemorySize, smem_bytes);
    dim3 grid((VOUT + 127) / 128, B_ / 128);
    k_scores<<<grid, 256, smem_bytes>>>(emb, out);
}

// round 6
// speedup vs baseline: 1.4710x; 1.1893x over previous
#include <cuda_runtime.h>
#include <cuda_bf16.h>
#include <math.h>
#include <stdint.h>

// Problem constants
#define B_   1024
#define N_   24
#define L_   24
#define D_   128
#define V_   40000
#define VOUT 39999           // V-1 output columns
#define VPAD 40064           // 313*128, padded vocab tiles
#define ALPHA_ 0.2f
#define NEG_ (-9e15f)

// ---------------- scratch (device globals; no runtime allocation) ----------------
static __device__ float g_Wc[384 * 128];
static __device__ float g_bc[128];
static __device__ float g_posw[24 * 128];
static __device__ float g_h[B_ * N_ * D_];
static __device__ float g_hagg[B_ * N_ * D_];
static __device__ __nv_bfloat16 g_selhi[B_ * D_];
static __device__ __nv_bfloat16 g_sello[B_ * D_];
static __device__ __nv_bfloat16 g_embhi[VPAD * D_];   // row v = emb[v+1] (hi)
static __device__ __nv_bfloat16 g_emblo[VPAD * D_];   // row v = emb[v+1] (lo)

// ==================== warp-MMA helpers (portable PTX, sm_80+) ====================
__device__ __forceinline__ uint32_t smem_u32(const void* p) {
    uint32_t a;
    asm("{ .reg .u64 t; cvta.to.shared.u64 t, %1; cvt.u32.u64 %0, t; }" : "=r"(a) : "l"(p));
    return a;
}
__device__ __forceinline__ void ldsm_x4(uint32_t* r, uint32_t addr) {
    asm volatile("ldmatrix.sync.aligned.m8n8.x4.shared.b16 {%0,%1,%2,%3}, [%4];"
                 : "=r"(r[0]), "=r"(r[1]), "=r"(r[2]), "=r"(r[3]) : "r"(addr));
}
__device__ __forceinline__ void mma_bf16(float* c, const uint32_t* a, const uint32_t* b) {
    asm volatile("mma.sync.aligned.m16n8k16.row.col.f32.bf16.bf16.f32 "
                 "{%0,%1,%2,%3}, {%4,%5,%6,%7}, {%8,%9}, {%0,%1,%2,%3};"
                 : "+f"(c[0]), "+f"(c[1]), "+f"(c[2]), "+f"(c[3])
                 : "r"(a[0]), "r"(a[1]), "r"(a[2]), "r"(a[3]), "r"(b[0]), "r"(b[1]));
}

// ====================================================================
// Kernel 0: fold weights + pos projection
// ====================================================================
__global__ void k_precompute(const float* __restrict__ W_img, const float* __restrict__ b_img,
                             const float* __restrict__ W_txt, const float* __restrict__ b_txt,
                             const float* __restrict__ W_fuse, const float* __restrict__ b_fuse,
                             const float* __restrict__ pos_emb, const float* __restrict__ w_1) {
    int row = blockIdx.x;
    int d = threadIdx.x;
    if (row < 128) {
        g_Wc[row * 128 + d] = W_fuse[row * 128 + d];
    } else if (row < 256) {
        int k = row - 128;
        float s = 0.f;
        #pragma unroll 4
        for (int j = 0; j < 128; ++j) s += W_img[k * 128 + j] * W_fuse[(128 + j) * 128 + d];
        g_Wc[row * 128 + d] = s;
    } else if (row < 384) {
        int k = row - 256;
        float s = 0.f;
        #pragma unroll 4
        for (int j = 0; j < 128; ++j) s += W_txt[k * 128 + j] * W_fuse[(256 + j) * 128 + d];
        g_Wc[row * 128 + d] = s;
    } else if (row == 384) {
        float s = b_fuse[d];
        #pragma unroll 4
        for (int j = 0; j < 128; ++j) {
            s += b_img[j] * W_fuse[(128 + j) * 128 + d];
            s += b_txt[j] * W_fuse[(256 + j) * 128 + d];
        }
        g_bc[d] = s;
    } else {
        int l = row - 385;
        const float* pr = pos_emb + (size_t)(23 - l) * 128;
        float s = 0.f;
        #pragma unroll 4
        for (int k = 0; k < 128; ++k) s += pr[k] * w_1[k * 128 + d];
        g_posw[l * 128 + d] = s;
    }
}

// ====================================================================
// Kernel 0b: split emb[1:] into bf16 hi/lo (padded to VPAD rows)
// ====================================================================
__global__ __launch_bounds__(256) void k_split_emb(const float* __restrict__ emb) {
    int idx = blockIdx.x * 256 + threadIdx.x;     // over VPAD*128
    int row = idx >> 7;
    int c = idx & 127;
    float x = (row < VOUT) ? emb[(size_t)(row + 1) * 128 + c] : 0.f;
    __nv_bfloat16 h = __float2bfloat16(x);
    g_embhi[idx] = h;
    g_emblo[idx] = __float2bfloat16(x - __bfloat162float(h));
}

// ====================================================================
// Kernel 1: fused multimodal embedding
// ====================================================================
__global__ __launch_bounds__(256) void k_embed(const int* __restrict__ items,
                                               const float* __restrict__ emb,
                                               const float* __restrict__ img_emb,
                                               const float* __restrict__ txt_emb) {
    __shared__ __align__(16) float Ash[32][132];
    __shared__ int ids[32];
    int rowbase = blockIdx.x * 32;
    int tid = threadIdx.x;
    int d = tid & 127;
    int rh = tid >> 7;
    int r0 = rh * 16;

    if (tid < 32) ids[tid] = items[rowbase + tid];

    float acc[16];
    #pragma unroll
    for (int i = 0; i < 16; ++i) acc[i] = 0.f;

    for (int c = 0; c < 3; ++c) {
        __syncthreads();
        const float* src = (c == 0) ? emb : (c == 1) ? img_emb : txt_emb;
        for (int idx = tid; idx < 32 * 128; idx += 256) {
            int r = idx >> 7, cc = idx & 127;
            Ash[r][cc] = src[(size_t)ids[r] * 128 + cc];
        }
        __syncthreads();
        const float* wc = g_Wc + (size_t)c * 128 * 128 + d;
        #pragma unroll 4
        for (int k = 0; k < 128; k += 4) {
            float w0 = wc[(size_t)(k + 0) * 128];
            float w1 = wc[(size_t)(k + 1) * 128];
            float w2 = wc[(size_t)(k + 2) * 128];
            float w3 = wc[(size_t)(k + 3) * 128];
            #pragma unroll
            for (int rr = 0; rr < 16; ++rr) {
                float4 s4 = *(const float4*)&Ash[r0 + rr][k];
                acc[rr] += s4.x * w0 + s4.y * w1 + s4.z * w2 + s4.w * w3;
            }
        }
    }
    float bias = g_bc[d];
    #pragma unroll
    for (int rr = 0; rr < 16; ++rr)
        g_h[(size_t)(rowbase + r0 + rr) * 128 + d] = acc[rr] + bias;
}

// ====================================================================
// Kernel 2: RGAT layer
// ====================================================================
__global__ __launch_bounds__(256) void k_rgat(const int* __restrict__ adj,
                                              const float* __restrict__ a_rel) {
    __shared__ __align__(16) float hsh[24][128];
    __shared__ float esh[24][24];
    __shared__ __align__(16) float arel[4][128];
    int b = blockIdx.x;
    int tid = threadIdx.x;

    for (int idx = tid; idx < 24 * 128; idx += 256)
        hsh[idx >> 7][idx & 127] = g_h[(size_t)b * (24 * 128) + idx];
    for (int idx = tid; idx < 4 * 128; idx += 256)
        arel[idx >> 7][idx & 127] = a_rel[idx];
    __syncthreads();

    for (int p = tid; p < 576; p += 256) {
        int i = p / 24, j = p % 24;
        int a = adj[b * 576 + p];
        float v;
        if (a == 0) {
            v = NEG_;
        } else {
            const float* ar = arel[a - 1];
            float s = 0.f;
            #pragma unroll 8
            for (int d2 = 0; d2 < 128; d2 += 4) {
                float4 hi = *(const float4*)&hsh[i][d2];
                float4 hj = *(const float4*)&hsh[j][d2];
                float4 aa = *(const float4*)&ar[d2];
                s += hi.x * hj.x * aa.x + hi.y * hj.y * aa.y
                   + hi.z * hj.z * aa.z + hi.w * hj.w * aa.w;
            }
            v = (s > 0.f) ? s : ALPHA_ * s;
        }
        esh[i][j] = v;
    }
    __syncthreads();

    if (tid < 24) {
        float mx = -INFINITY;
        #pragma unroll
        for (int j = 0; j < 24; ++j) mx = fmaxf(mx, esh[tid][j]);
        float sum = 0.f;
        #pragma unroll
        for (int j = 0; j < 24; ++j) {
            float e = expf(esh[tid][j] - mx);
            esh[tid][j] = e;
            sum += e;
        }
        float inv = 1.f / sum;
        #pragma unroll
        for (int j = 0; j < 24; ++j) esh[tid][j] *= inv;
    }
    __syncthreads();

    for (int idx = tid; idx < 24 * 128; idx += 256) {
        int i = idx >> 7, d2 = idx & 127;
        float s = 0.f;
        #pragma unroll
        for (int j = 0; j < 24; ++j) s += esh[i][j] * hsh[j][d2];
        g_hagg[(size_t)b * (24 * 128) + idx] = s;
    }
}

// ====================================================================
// Kernel 3: session readout (k-outer), writes bf16 hi/lo select
// ====================================================================
__global__ __launch_bounds__(128) void k_readout(const int* __restrict__ alias_,
                                                 const int* __restrict__ mask_,
                                                 const float* __restrict__ w_1,
                                                 const float* __restrict__ w_2,
                                                 const float* __restrict__ glu1_w,
                                                 const float* __restrict__ glu1_b,
                                                 const float* __restrict__ glu2_w) {
    __shared__ __align__(16) float seq[24][128];
    __shared__ __align__(16) float nhsh[24][128];
    __shared__ float hssh[128];
    __shared__ int al[24];
    __shared__ float mk[24];
    __shared__ float betash[24];
    int b = blockIdx.x;
    int d = threadIdx.x;

    if (d < 24) {
        al[d] = alias_[b * 24 + d];
        mk[d] = (float)mask_[b * 24 + d];
    }
    __syncthreads();
    #pragma unroll
    for (int l = 0; l < 24; ++l)
        seq[l][d] = g_hagg[((size_t)b * 24 + al[l]) * 128 + d];
    __syncthreads();

    float msum = 0.f, hs = 0.f;
    #pragma unroll
    for (int l = 0; l < 24; ++l) { msum += mk[l]; hs += mk[l] * seq[l][d]; }
    hs /= fmaxf(msum, 1.f);
    hssh[d] = hs;
    __syncthreads();

    float hsg = 0.f;
    #pragma unroll 4
    for (int k = 0; k < 128; ++k) hsg += hssh[k] * glu2_w[k * 128 + d];

    float acc[24];
    #pragma unroll
    for (int l = 0; l < 24; ++l) acc[l] = g_posw[l * 128 + d];

    #pragma unroll 2
    for (int k = 0; k < 128; k += 4) {
        float w0 = w_1[(128 + k + 0) * 128 + d];
        float w1 = w_1[(128 + k + 1) * 128 + d];
        float w2c = w_1[(128 + k + 2) * 128 + d];
        float w3 = w_1[(128 + k + 3) * 128 + d];
        #pragma unroll
        for (int l = 0; l < 24; ++l) {
            float4 s4 = *(const float4*)&seq[l][k];
            acc[l] += s4.x * w0 + s4.y * w1 + s4.z * w2c + s4.w * w3;
        }
    }
    #pragma unroll
    for (int l = 0; l < 24; ++l) nhsh[l][d] = tanhf(acc[l]);
    __syncthreads();

    float base = glu1_b[d] + hsg;
    #pragma unroll
    for (int l = 0; l < 24; ++l) acc[l] = base;

    #pragma unroll 2
    for (int k = 0; k < 128; k += 4) {
        float w0 = glu1_w[(k + 0) * 128 + d];
        float w1 = glu1_w[(k + 1) * 128 + d];
        float w2c = glu1_w[(k + 2) * 128 + d];
        float w3 = glu1_w[(k + 3) * 128 + d];
        #pragma unroll
        for (int l = 0; l < 24; ++l) {
            float4 s4 = *(const float4*)&nhsh[l][k];
            acc[l] += s4.x * w0 + s4.y * w1 + s4.z * w2c + s4.w * w3;
        }
    }
    float w2d = w_2[d];
    __syncthreads();
    #pragma unroll
    for (int l = 0; l < 24; ++l)
        nhsh[l][d] = (1.f / (1.f + expf(-acc[l]))) * w2d;
    __syncthreads();

    if (d < 24) {
        float s = 0.f;
        #pragma unroll 8
        for (int k = 0; k < 128; k += 4) {
            float4 p4 = *(const float4*)&nhsh[d][k];
            s += p4.x + p4.y + p4.z + p4.w;
        }
        betash[d] = s * mk[d];
    }
    __syncthreads();

    float sel = 0.f;
    #pragma unroll
    for (int l = 0; l < 24; ++l) sel += betash[l] * seq[l][d];

    __nv_bfloat16 h = __float2bfloat16(sel);
    g_selhi[b * 128 + d] = h;
    g_sello[b * 128 + d] = __float2bfloat16(sel - __bfloat162float(h));
}

// ====================================================================
// Kernel 4: scores via warp-level bf16 mma.sync, split-3 terms.
// CTA = 128m x 128n. 8 warps: 4(m) x 2(n); warp = 32m x 64n.
// smem: 4 tiles [128][136] bf16 (Ahi, Alo, Bhi, Blo) = 139264 B.
// D = Ah*Bh + Ah*Bl + Al*Bh  (fp32 accumulate)
// ====================================================================
#define PADK 136
#define TILE_ELEMS (128 * PADK)

__device__ __forceinline__ void fill_tile(__nv_bfloat16* dst, const __nv_bfloat16* __restrict__ src,
                                          int tid) {
    // 128 rows x 128 bf16 = 2048 uint4 chunks; dst rows padded to 136 bf16 (272 B)
    for (int i = tid; i < 2048; i += 256) {
        int r = i >> 4;
        int c = i & 15;
        uint4 v = *(const uint4*)(src + (size_t)r * 128 + c * 8);
        *(uint4*)((char*)dst + r * (PADK * 2) + c * 16) = v;
    }
}

__global__ __launch_bounds__(256) void k_scores_mma(float* __restrict__ out) {
    extern __shared__ __align__(16) __nv_bfloat16 smem[];
    __nv_bfloat16* Ahs = smem;
    __nv_bfloat16* Als = Ahs + TILE_ELEMS;
    __nv_bfloat16* Bhs = Als + TILE_ELEMS;
    __nv_bfloat16* Bls = Bhs + TILE_ELEMS;

    int tid = threadIdx.x;
    int v0 = blockIdx.x * 128;
    int m0 = blockIdx.y * 128;

    fill_tile(Ahs, g_selhi + (size_t)m0 * 128, tid);
    fill_tile(Als, g_sello + (size_t)m0 * 128, tid);
    fill_tile(Bhs, g_embhi + (size_t)v0 * 128, tid);
    fill_tile(Bls, g_emblo + (size_t)v0 * 128, tid);
    __syncthreads();

    int wid = tid >> 5, lid = tid & 31;
    int wm = (wid & 3) * 32;     // warp m offset
    int wn = (wid >> 2) * 64;    // warp n offset

    uint32_t aH = smem_u32(Ahs), aL = smem_u32(Als);
    uint32_t bH = smem_u32(Bhs), bL = smem_u32(Bls);

    float c[2][8][4];
    #pragma unroll
    for (int mi = 0; mi < 2; ++mi)
        #pragma unroll
        for (int ni = 0; ni < 8; ++ni)
            #pragma unroll
            for (int j = 0; j < 4; ++j) c[mi][ni][j] = 0.f;

    // per-lane ldmatrix address offsets (element coords -> bytes)
    // A (x4 = one m16k16 frag): matrix g=lid/8: row_off=(g&1)*8, k_off=(g>>1)*8
    int a_row = ((lid >> 3) & 1) * 8 + (lid & 7);
    int a_kof = ((lid >> 4) & 1) * 8;
    // B (x4 = two n8k16 frags over 16 n): matrix g: n_off=(g>>1)*8, k_off=(g&1)*8
    int b_n = ((lid >> 4) & 1) * 8 + (lid & 7);
    int b_kof = ((lid >> 3) & 1) * 8;

    #pragma unroll
    for (int kb = 0; kb < 128; kb += 16) {
        uint32_t ah[2][4], al[2][4], bh[8][2], bl[8][2];
        #pragma unroll
        for (int mi = 0; mi < 2; ++mi) {
            uint32_t off = (uint32_t)((wm + mi * 16 + a_row) * PADK + kb + a_kof) * 2;
            ldsm_x4(ah[mi], aH + off);
            ldsm_x4(al[mi], aL + off);
        }
        #pragma unroll
        for (int jj = 0; jj < 4; ++jj) {
            uint32_t off = (uint32_t)((wn + jj * 16 + b_n) * PADK + kb + b_kof) * 2;
            uint32_t r[4];
            ldsm_x4(r, bH + off);
            bh[2 * jj][0] = r[0]; bh[2 * jj][1] = r[1];
            bh[2 * jj + 1][0] = r[2]; bh[2 * jj + 1][1] = r[3];
            ldsm_x4(r, bL + off);
            bl[2 * jj][0] = r[0]; bl[2 * jj][1] = r[1];
            bl[2 * jj + 1][0] = r[2]; bl[2 * jj + 1][1] = r[3];
        }
        #pragma unroll
        for (int mi = 0; mi < 2; ++mi)
            #pragma unroll
            for (int ni = 0; ni < 8; ++ni) {
                mma_bf16(c[mi][ni], ah[mi], bh[ni]);
                mma_bf16(c[mi][ni], ah[mi], bl[ni]);
                mma_bf16(c[mi][ni], al[mi], bh[ni]);
            }
    }

    // store fragments (quad of lanes covers 8 consecutive cols -> 32B sectors)
    int r0 = m0 + wm + (lid >> 2);
    int c0 = v0 + wn + (lid & 3) * 2;
    #pragma unroll
    for (int mi = 0; mi < 2; ++mi) {
        float* p0 = out + (size_t)(r0 + mi * 16) * VOUT;
        float* p1 = out + (size_t)(r0 + mi * 16 + 8) * VOUT;
        #pragma unroll
        for (int ni = 0; ni < 8; ++ni) {
            int gc = c0 + ni * 8;
            if (gc < VOUT)     p0[gc]     = c[mi][ni][0];
            if (gc + 1 < VOUT) p0[gc + 1] = c[mi][ni][1];
            if (gc < VOUT)     p1[gc]     = c[mi][ni][2];
            if (gc + 1 < VOUT) p1[gc + 1] = c[mi][ni][3];
        }
    }
}

// ====================================================================
// launch
// ====================================================================
extern "C" void kernel_launch(void* const* d_in, const int* in_sizes, int n_in,
                              void* d_out, int out_size) {
    const int*   items   = (const int*)d_in[0];
    const int*   adj     = (const int*)d_in[1];
    const int*   alias_  = (const int*)d_in[2];
    const int*   mask_   = (const int*)d_in[3];
    const float* emb     = (const float*)d_in[4];
    const float* img_emb = (const float*)d_in[5];
    const float* txt_emb = (const float*)d_in[6];
    const float* W_img   = (const float*)d_in[7];
    const float* b_img   = (const float*)d_in[8];
    const float* W_txt   = (const float*)d_in[9];
    const float* b_txt   = (const float*)d_in[10];
    const float* W_fuse  = (const float*)d_in[11];
    const float* b_fuse  = (const float*)d_in[12];
    const float* a_rel   = (const float*)d_in[13];
    const float* pos_emb = (const float*)d_in[14];
    const float* w_1     = (const float*)d_in[15];
    const float* w_2     = (const float*)d_in[16];
    const float* glu1_w  = (const float*)d_in[17];
    const float* glu1_b  = (const float*)d_in[18];
    const float* glu2_w  = (const float*)d_in[19];
    float* out = (float*)d_out;

    k_precompute<<<409, 128>>>(W_img, b_img, W_txt, b_txt, W_fuse, b_fuse, pos_emb, w_1);
    k_split_emb<<<(VPAD * 128) / 256, 256>>>(emb);
    k_embed<<<(B_ * N_) / 32, 256>>>(items, emb, img_emb, txt_emb);
    k_rgat<<<B_, 256>>>(adj, a_rel);
    k_readout<<<B_, 128>>>(alias_, mask_, w_1, w_2, glu1_w, glu1_b, glu2_w);

    int smem_bytes = 4 * TILE_ELEMS * (int)sizeof(__nv_bfloat16);  // 139264
    cudaFuncSetAttribute(k_scores_mma, cudaFuncAttributeMaxDynamicSharedMemorySize, smem_bytes);
    dim3 grid(VPAD / 128, B_ / 128);   // 313 x 8
    k_scores_mma<<<grid, 256, smem_bytes>>>(out);
}

// round 8
// speedup vs baseline: 1.5808x; 1.0747x over previous
#include <cuda_runtime.h>
#include <cuda_bf16.h>
#include <math.h>
#include <stdint.h>

// Problem constants
#define B_   1024
#define N_   24
#define L_   24
#define D_   128
#define V_   40000
#define VOUT 39999           // V-1 output columns
#define VPAD 40064           // 313*128, padded vocab tiles
#define ALPHA_ 0.2f
#define NEG_ (-9e15f)

// ---------------- scratch (device globals; no runtime allocation) ----------------
static __device__ float g_Wc[384 * 128];
static __device__ float g_bc[128];
static __device__ float g_posw[24 * 128];
static __device__ float g_h[B_ * N_ * D_];
static __device__ float g_hagg[B_ * N_ * D_];
static __device__ __nv_bfloat16 g_selhi[B_ * D_];
static __device__ __nv_bfloat16 g_sello[B_ * D_];
static __device__ __nv_bfloat16 g_embhi[VPAD * D_];   // row v = emb[v+1] (hi)
static __device__ __nv_bfloat16 g_emblo[VPAD * D_];   // row v = emb[v+1] (lo)

// ==================== warp-MMA helpers (portable PTX, sm_80+) ====================
__device__ __forceinline__ uint32_t smem_u32(const void* p) {
    uint32_t a;
    asm("{ .reg .u64 t; cvta.to.shared.u64 t, %1; cvt.u32.u64 %0, t; }" : "=r"(a) : "l"(p));
    return a;
}
__device__ __forceinline__ void ldsm_x4(uint32_t* r, uint32_t addr) {
    asm volatile("ldmatrix.sync.aligned.m8n8.x4.shared.b16 {%0,%1,%2,%3}, [%4];"
                 : "=r"(r[0]), "=r"(r[1]), "=r"(r[2]), "=r"(r[3]) : "r"(addr));
}
__device__ __forceinline__ void mma_bf16(float* c, const uint32_t* a, const uint32_t* b) {
    asm volatile("mma.sync.aligned.m16n8k16.row.col.f32.bf16.bf16.f32 "
                 "{%0,%1,%2,%3}, {%4,%5,%6,%7}, {%8,%9}, {%0,%1,%2,%3};"
                 : "+f"(c[0]), "+f"(c[1]), "+f"(c[2]), "+f"(c[3])
                 : "r"(a[0]), "r"(a[1]), "r"(a[2]), "r"(a[3]), "r"(b[0]), "r"(b[1]));
}

// ====================================================================
// Kernel 0: fold weights + pos projection
// ====================================================================
__global__ void k_precompute(const float* __restrict__ W_img, const float* __restrict__ b_img,
                             const float* __restrict__ W_txt, const float* __restrict__ b_txt,
                             const float* __restrict__ W_fuse, const float* __restrict__ b_fuse,
                             const float* __restrict__ pos_emb, const float* __restrict__ w_1) {
    int row = blockIdx.x;
    int d = threadIdx.x;
    if (row < 128) {
        g_Wc[row * 128 + d] = W_fuse[row * 128 + d];
    } else if (row < 256) {
        int k = row - 128;
        float s = 0.f;
        #pragma unroll 4
        for (int j = 0; j < 128; ++j) s += W_img[k * 128 + j] * W_fuse[(128 + j) * 128 + d];
        g_Wc[row * 128 + d] = s;
    } else if (row < 384) {
        int k = row - 256;
        float s = 0.f;
        #pragma unroll 4
        for (int j = 0; j < 128; ++j) s += W_txt[k * 128 + j] * W_fuse[(256 + j) * 128 + d];
        g_Wc[row * 128 + d] = s;
    } else if (row == 384) {
        float s = b_fuse[d];
        #pragma unroll 4
        for (int j = 0; j < 128; ++j) {
            s += b_img[j] * W_fuse[(128 + j) * 128 + d];
            s += b_txt[j] * W_fuse[(256 + j) * 128 + d];
        }
        g_bc[d] = s;
    } else {
        int l = row - 385;
        const float* pr = pos_emb + (size_t)(23 - l) * 128;
        float s = 0.f;
        #pragma unroll 4
        for (int k = 0; k < 128; ++k) s += pr[k] * w_1[k * 128 + d];
        g_posw[l * 128 + d] = s;
    }
}

// ====================================================================
// Kernel 0b: split emb[1:] into bf16 hi/lo (padded to VPAD rows)
// ====================================================================
__global__ __launch_bounds__(256) void k_split_emb(const float* __restrict__ emb) {
    int idx = blockIdx.x * 256 + threadIdx.x;     // over VPAD*128
    int row = idx >> 7;
    int c = idx & 127;
    float x = (row < VOUT) ? emb[(size_t)(row + 1) * 128 + c] : 0.f;
    __nv_bfloat16 h = __float2bfloat16(x);
    g_embhi[idx] = h;
    g_emblo[idx] = __float2bfloat16(x - __bfloat162float(h));
}

// ====================================================================
// Kernel 1: fused multimodal embedding
// ====================================================================
__global__ __launch_bounds__(256) void k_embed(const int* __restrict__ items,
                                               const float* __restrict__ emb,
                                               const float* __restrict__ img_emb,
                                               const float* __restrict__ txt_emb) {
    __shared__ __align__(16) float Ash[32][132];
    __shared__ int ids[32];
    int rowbase = blockIdx.x * 32;
    int tid = threadIdx.x;
    int d = tid & 127;
    int rh = tid >> 7;
    int r0 = rh * 16;

    if (tid < 32) ids[tid] = items[rowbase + tid];

    float acc[16];
    #pragma unroll
    for (int i = 0; i < 16; ++i) acc[i] = 0.f;

    for (int c = 0; c < 3; ++c) {
        __syncthreads();
        const float* src = (c == 0) ? emb : (c == 1) ? img_emb : txt_emb;
        for (int idx = tid; idx < 32 * 128; idx += 256) {
            int r = idx >> 7, cc = idx & 127;
            Ash[r][cc] = src[(size_t)ids[r] * 128 + cc];
        }
        __syncthreads();
        const float* wc = g_Wc + (size_t)c * 128 * 128 + d;
        #pragma unroll 4
        for (int k = 0; k < 128; k += 4) {
            float w0 = wc[(size_t)(k + 0) * 128];
            float w1 = wc[(size_t)(k + 1) * 128];
            float w2 = wc[(size_t)(k + 2) * 128];
            float w3 = wc[(size_t)(k + 3) * 128];
            #pragma unroll
            for (int rr = 0; rr < 16; ++rr) {
                float4 s4 = *(const float4*)&Ash[r0 + rr][k];
                acc[rr] += s4.x * w0 + s4.y * w1 + s4.z * w2 + s4.w * w3;
            }
        }
    }
    float bias = g_bc[d];
    #pragma unroll
    for (int rr = 0; rr < 16; ++rr)
        g_h[(size_t)(rowbase + r0 + rr) * 128 + d] = acc[rr] + bias;
}

// ====================================================================
// Kernel 2: RGAT layer — warp-per-pair e-computation (conflict-free).
// ====================================================================
__global__ __launch_bounds__(256) void k_rgat(const int* __restrict__ adj,
                                              const float* __restrict__ a_rel) {
    __shared__ __align__(16) float hsh[24][132];    // padded: bank rotation 4/row
    __shared__ float esh[24][24];
    __shared__ __align__(16) float arel[4][132];
    __shared__ int adjs[576];
    int b = blockIdx.x;
    int tid = threadIdx.x;
    int wid = tid >> 5, lane = tid & 31;

    for (int idx = tid; idx < 24 * 128; idx += 256)
        hsh[idx >> 7][idx & 127] = g_h[(size_t)b * (24 * 128) + idx];
    for (int idx = tid; idx < 4 * 128; idx += 256)
        arel[idx >> 7][idx & 127] = a_rel[idx];
    for (int idx = tid; idx < 576; idx += 256)
        adjs[idx] = adj[b * 576 + idx];
    __syncthreads();

    // one warp per (i,j) pair; lanes split the 128-dim product 4-wide
    int d4 = lane * 4;
    for (int p = wid; p < 576; p += 8) {
        int i = p / 24, j = p - i * 24;
        int a = adjs[p];                      // warp-uniform
        float v = NEG_;
        if (a != 0) {
            float4 hi = *(const float4*)&hsh[i][d4];
            float4 hj = *(const float4*)&hsh[j][d4];
            float4 aa = *(const float4*)&arel[a - 1][d4];
            float s = hi.x * hj.x * aa.x + hi.y * hj.y * aa.y
                    + hi.z * hj.z * aa.z + hi.w * hj.w * aa.w;
            #pragma unroll
            for (int off = 16; off > 0; off >>= 1)
                s += __shfl_xor_sync(0xffffffffu, s, off);
            v = (s > 0.f) ? s : ALPHA_ * s;
        }
        if (lane == 0) esh[i][j] = v;
    }
    __syncthreads();

    if (tid < 24) {
        float mx = -INFINITY;
        #pragma unroll
        for (int j = 0; j < 24; ++j) mx = fmaxf(mx, esh[tid][j]);
        float sum = 0.f;
        #pragma unroll
        for (int j = 0; j < 24; ++j) {
            float e = expf(esh[tid][j] - mx);
            esh[tid][j] = e;
            sum += e;
        }
        float inv = 1.f / sum;
        #pragma unroll
        for (int j = 0; j < 24; ++j) esh[tid][j] *= inv;
    }
    __syncthreads();

    for (int idx = tid; idx < 24 * 128; idx += 256) {
        int i = idx >> 7, d2 = idx & 127;
        float s = 0.f;
        #pragma unroll
        for (int j = 0; j < 24; ++j) s += esh[i][j] * hsh[j][d2];
        g_hagg[(size_t)b * (24 * 128) + idx] = s;
    }
}

// ====================================================================
// Kernel 3: session readout (k-outer), writes bf16 hi/lo select
// ====================================================================
__global__ __launch_bounds__(128) void k_readout(const int* __restrict__ alias_,
                                                 const int* __restrict__ mask_,
                                                 const float* __restrict__ w_1,
                                                 const float* __restrict__ w_2,
                                                 const float* __restrict__ glu1_w,
                                                 const float* __restrict__ glu1_b,
                                                 const float* __restrict__ glu2_w) {
    __shared__ __align__(16) float seq[24][128];
    __shared__ __align__(16) float nhsh[24][128];
    __shared__ float hssh[128];
    __shared__ int al[24];
    __shared__ float mk[24];
    __shared__ float betash[24];
    int b = blockIdx.x;
    int d = threadIdx.x;

    if (d < 24) {
        al[d] = alias_[b * 24 + d];
        mk[d] = (float)mask_[b * 24 + d];
    }
    __syncthreads();
    #pragma unroll
    for (int l = 0; l < 24; ++l)
        seq[l][d] = g_hagg[((size_t)b * 24 + al[l]) * 128 + d];
    __syncthreads();

    float msum = 0.f, hs = 0.f;
    #pragma unroll
    for (int l = 0; l < 24; ++l) { msum += mk[l]; hs += mk[l] * seq[l][d]; }
    hs /= fmaxf(msum, 1.f);
    hssh[d] = hs;
    __syncthreads();

    float hsg = 0.f;
    #pragma unroll 4
    for (int k = 0; k < 128; ++k) hsg += hssh[k] * glu2_w[k * 128 + d];

    float acc[24];
    #pragma unroll
    for (int l = 0; l < 24; ++l) acc[l] = g_posw[l * 128 + d];

    #pragma unroll 2
    for (int k = 0; k < 128; k += 4) {
        float w0 = w_1[(128 + k + 0) * 128 + d];
        float w1 = w_1[(128 + k + 1) * 128 + d];
        float w2c = w_1[(128 + k + 2) * 128 + d];
        float w3 = w_1[(128 + k + 3) * 128 + d];
        #pragma unroll
        for (int l = 0; l < 24; ++l) {
            float4 s4 = *(const float4*)&seq[l][k];
            acc[l] += s4.x * w0 + s4.y * w1 + s4.z * w2c + s4.w * w3;
        }
    }
    #pragma unroll
    for (int l = 0; l < 24; ++l) nhsh[l][d] = tanhf(acc[l]);
    __syncthreads();

    float base = glu1_b[d] + hsg;
    #pragma unroll
    for (int l = 0; l < 24; ++l) acc[l] = base;

    #pragma unroll 2
    for (int k = 0; k < 128; k += 4) {
        float w0 = glu1_w[(k + 0) * 128 + d];
        float w1 = glu1_w[(k + 1) * 128 + d];
        float w2c = glu1_w[(k + 2) * 128 + d];
        float w3 = glu1_w[(k + 3) * 128 + d];
        #pragma unroll
        for (int l = 0; l < 24; ++l) {
            float4 s4 = *(const float4*)&nhsh[l][k];
            acc[l] += s4.x * w0 + s4.y * w1 + s4.z * w2c + s4.w * w3;
        }
    }
    float w2d = w_2[d];
    __syncthreads();
    #pragma unroll
    for (int l = 0; l < 24; ++l)
        nhsh[l][d] = (1.f / (1.f + expf(-acc[l]))) * w2d;
    __syncthreads();

    if (d < 24) {
        float s = 0.f;
        #pragma unroll 8
        for (int k = 0; k < 128; k += 4) {
            float4 p4 = *(const float4*)&nhsh[d][k];
            s += p4.x + p4.y + p4.z + p4.w;
        }
        betash[d] = s * mk[d];
    }
    __syncthreads();

    float sel = 0.f;
    #pragma unroll
    for (int l = 0; l < 24; ++l) sel += betash[l] * seq[l][d];

    __nv_bfloat16 h = __float2bfloat16(sel);
    g_selhi[b * 128 + d] = h;
    g_sello[b * 128 + d] = __float2bfloat16(sel - __bfloat162float(h));
}

// ====================================================================
// Kernel 4: scores via warp-level bf16 mma.sync, split-3 terms.
// CTA = 128m x 128n. 8 warps: 4(m) x 2(n); warp = 32m x 64n.
// smem: 4 tiles [128][136] bf16 (Ahi, Alo, Bhi, Blo) = 139264 B.
// D = Ah*Bh + Ah*Bl + Al*Bh  (fp32 accumulate)
// ====================================================================
#define PADK 136
#define TILE_ELEMS (128 * PADK)

__device__ __forceinline__ void fill_tile(__nv_bfloat16* dst, const __nv_bfloat16* __restrict__ src,
                                          int tid) {
    for (int i = tid; i < 2048; i += 256) {
        int r = i >> 4;
        int c = i & 15;
        uint4 v = *(const uint4*)(src + (size_t)r * 128 + c * 8);
        *(uint4*)((char*)dst + r * (PADK * 2) + c * 16) = v;
    }
}

__global__ __launch_bounds__(256) void k_scores_mma(float* __restrict__ out) {
    extern __shared__ __align__(16) __nv_bfloat16 smem[];
    __nv_bfloat16* Ahs = smem;
    __nv_bfloat16* Als = Ahs + TILE_ELEMS;
    __nv_bfloat16* Bhs = Als + TILE_ELEMS;
    __nv_bfloat16* Bls = Bhs + TILE_ELEMS;

    int tid = threadIdx.x;
    int v0 = blockIdx.x * 128;
    int m0 = blockIdx.y * 128;

    fill_tile(Ahs, g_selhi + (size_t)m0 * 128, tid);
    fill_tile(Als, g_sello + (size_t)m0 * 128, tid);
    fill_tile(Bhs, g_embhi + (size_t)v0 * 128, tid);
    fill_tile(Bls, g_emblo + (size_t)v0 * 128, tid);
    __syncthreads();

    int wid = tid >> 5, lid = tid & 31;
    int wm = (wid & 3) * 32;     // warp m offset
    int wn = (wid >> 2) * 64;    // warp n offset

    uint32_t aH = smem_u32(Ahs), aL = smem_u32(Als);
    uint32_t bH = smem_u32(Bhs), bL = smem_u32(Bls);

    float c[2][8][4];
    #pragma unroll
    for (int mi = 0; mi < 2; ++mi)
        #pragma unroll
        for (int ni = 0; ni < 8; ++ni)
            #pragma unroll
            for (int j = 0; j < 4; ++j) c[mi][ni][j] = 0.f;

    int a_row = ((lid >> 3) & 1) * 8 + (lid & 7);
    int a_kof = ((lid >> 4) & 1) * 8;
    int b_n = ((lid >> 4) & 1) * 8 + (lid & 7);
    int b_kof = ((lid >> 3) & 1) * 8;

    #pragma unroll
    for (int kb = 0; kb < 128; kb += 16) {
        uint32_t ah[2][4], al[2][4], bh[8][2], bl[8][2];
        #pragma unroll
        for (int mi = 0; mi < 2; ++mi) {
            uint32_t off = (uint32_t)((wm + mi * 16 + a_row) * PADK + kb + a_kof) * 2;
            ldsm_x4(ah[mi], aH + off);
            ldsm_x4(al[mi], aL + off);
        }
        #pragma unroll
        for (int jj = 0; jj < 4; ++jj) {
            uint32_t off = (uint32_t)((wn + jj * 16 + b_n) * PADK + kb + b_kof) * 2;
            uint32_t r[4];
            ldsm_x4(r, bH + off);
            bh[2 * jj][0] = r[0]; bh[2 * jj][1] = r[1];
            bh[2 * jj + 1][0] = r[2]; bh[2 * jj + 1][1] = r[3];
            ldsm_x4(r, bL + off);
            bl[2 * jj][0] = r[0]; bl[2 * jj][1] = r[1];
            bl[2 * jj + 1][0] = r[2]; bl[2 * jj + 1][1] = r[3];
        }
        #pragma unroll
        for (int mi = 0; mi < 2; ++mi)
            #pragma unroll
            for (int ni = 0; ni < 8; ++ni) {
                mma_bf16(c[mi][ni], ah[mi], bh[ni]);
                mma_bf16(c[mi][ni], ah[mi], bl[ni]);
                mma_bf16(c[mi][ni], al[mi], bh[ni]);
            }
    }

    int r0 = m0 + wm + (lid >> 2);
    int c0 = v0 + wn + (lid & 3) * 2;
    #pragma unroll
    for (int mi = 0; mi < 2; ++mi) {
        float* p0 = out + (size_t)(r0 + mi * 16) * VOUT;
        float* p1 = out + (size_t)(r0 + mi * 16 + 8) * VOUT;
        #pragma unroll
        for (int ni = 0; ni < 8; ++ni) {
            int gc = c0 + ni * 8;
            if (gc < VOUT)     p0[gc]     = c[mi][ni][0];
            if (gc + 1 < VOUT) p0[gc + 1] = c[mi][ni][1];
            if (gc < VOUT)     p1[gc]     = c[mi][ni][2];
            if (gc + 1 < VOUT) p1[gc + 1] = c[mi][ni][3];
        }
    }
}

// ====================================================================
// launch
// ====================================================================
extern "C" void kernel_launch(void* const* d_in, const int* in_sizes, int n_in,
                              void* d_out, int out_size) {
    const int*   items   = (const int*)d_in[0];
    const int*   adj     = (const int*)d_in[1];
    const int*   alias_  = (const int*)d_in[2];
    const int*   mask_   = (const int*)d_in[3];
    const float* emb     = (const float*)d_in[4];
    const float* img_emb = (const float*)d_in[5];
    const float* txt_emb = (const float*)d_in[6];
    const float* W_img   = (const float*)d_in[7];
    const float* b_img   = (const float*)d_in[8];
    const float* W_txt   = (const float*)d_in[9];
    const float* b_txt   = (const float*)d_in[10];
    const float* W_fuse  = (const float*)d_in[11];
    const float* b_fuse  = (const float*)d_in[12];
    const float* a_rel   = (const float*)d_in[13];
    const float* pos_emb = (const float*)d_in[14];
    const float* w_1     = (const float*)d_in[15];
    const float* w_2     = (const float*)d_in[16];
    const float* glu1_w  = (const float*)d_in[17];
    const float* glu1_b  = (const float*)d_in[18];
    const float* glu2_w  = (const float*)d_in[19];
    float* out = (float*)d_out;

    k_precompute<<<409, 128>>>(W_img, b_img, W_txt, b_txt, W_fuse, b_fuse, pos_emb, w_1);
    k_split_emb<<<(VPAD * 128) / 256, 256>>>(emb);
    k_embed<<<(B_ * N_) / 32, 256>>>(items, emb, img_emb, txt_emb);
    k_rgat<<<B_, 256>>>(adj, a_rel);
    k_readout<<<B_, 128>>>(alias_, mask_, w_1, w_2, glu1_w, glu1_b, glu2_w);

    int smem_bytes = 4 * TILE_ELEMS * (int)sizeof(__nv_bfloat16);  // 139264
    cudaFuncSetAttribute(k_scores_mma, cudaFuncAttributeMaxDynamicSharedMemorySize, smem_bytes);
    dim3 grid(VPAD / 128, B_ / 128);   // 313 x 8
    k_scores_mma<<<grid, 256, smem_bytes>>>(out);
}

// round 11
// speedup vs baseline: 1.9025x; 1.2035x over previous
#include <cuda_runtime.h>
#include <cuda_bf16.h>
#include <math.h>
#include <stdint.h>

// Problem constants
#define B_   1024
#define N_   24
#define L_   24
#define D_   128
#define V_   40000
#define VOUT 39999           // V-1 output columns
#define VPAD 40064           // 313*128, padded vocab tiles
#define NTILES 313
#define GX 18                // n-tile groups (144 CTAs total, ~1 wave)
#define ALPHA_ 0.2f
#define NEG_ (-9e15f)

// ---------------- scratch (device globals; no runtime allocation) ----------------
static __device__ float g_Wc[384 * 128];
static __device__ float g_bc[128];
static __device__ float g_posw[24 * 128];
static __device__ float g_h[B_ * N_ * D_];
static __device__ float g_hagg[B_ * N_ * D_];
static __device__ __nv_bfloat16 g_selhi[B_ * D_];
static __device__ __nv_bfloat16 g_sello[B_ * D_];
static __device__ __nv_bfloat16 g_embhi[VPAD * D_];   // row v = emb[v+1] (hi)
static __device__ __nv_bfloat16 g_emblo[VPAD * D_];   // row v = emb[v+1] (lo)

// ==================== warp-MMA / async-copy helpers (portable PTX, sm_80+) ====================
__device__ __forceinline__ uint32_t smem_u32(const void* p) {
    uint32_t a;
    asm("{ .reg .u64 t; cvta.to.shared.u64 t, %1; cvt.u32.u64 %0, t; }" : "=r"(a) : "l"(p));
    return a;
}
__device__ __forceinline__ void ldsm_x4(uint32_t* r, uint32_t addr) {
    asm volatile("ldmatrix.sync.aligned.m8n8.x4.shared.b16 {%0,%1,%2,%3}, [%4];"
                 : "=r"(r[0]), "=r"(r[1]), "=r"(r[2]), "=r"(r[3]) : "r"(addr));
}
__device__ __forceinline__ void mma_bf16(float* c, const uint32_t* a, const uint32_t* b) {
    asm volatile("mma.sync.aligned.m16n8k16.row.col.f32.bf16.bf16.f32 "
                 "{%0,%1,%2,%3}, {%4,%5,%6,%7}, {%8,%9}, {%0,%1,%2,%3};"
                 : "+f"(c[0]), "+f"(c[1]), "+f"(c[2]), "+f"(c[3])
                 : "r"(a[0]), "r"(a[1]), "r"(a[2]), "r"(a[3]), "r"(b[0]), "r"(b[1]));
}
__device__ __forceinline__ void cpa16(uint32_t sa, const void* g) {
    asm volatile("{\n\t.reg .u64 gg;\n\tcvta.to.global.u64 gg, %1;\n\t"
                 "cp.async.cg.shared.global [%0], [gg], 16;\n\t}"
                 :: "r"(sa), "l"(g) : "memory");
}
#define CP_COMMIT() asm volatile("cp.async.commit_group;" ::: "memory")
#define CP_WAIT1()  asm volatile("cp.async.wait_group 1;" ::: "memory")

// ====================================================================
// Kernel 0: fold weights + pos projection
// ====================================================================
__global__ void k_precompute(const float* __restrict__ W_img, const float* __restrict__ b_img,
                             const float* __restrict__ W_txt, const float* __restrict__ b_txt,
                             const float* __restrict__ W_fuse, const float* __restrict__ b_fuse,
                             const float* __restrict__ pos_emb, const float* __restrict__ w_1) {
    int row = blockIdx.x;
    int d = threadIdx.x;
    if (row < 128) {
        g_Wc[row * 128 + d] = W_fuse[row * 128 + d];
    } else if (row < 256) {
        int k = row - 128;
        float s = 0.f;
        #pragma unroll 4
        for (int j = 0; j < 128; ++j) s += W_img[k * 128 + j] * W_fuse[(128 + j) * 128 + d];
        g_Wc[row * 128 + d] = s;
    } else if (row < 384) {
        int k = row - 256;
        float s = 0.f;
        #pragma unroll 4
        for (int j = 0; j < 128; ++j) s += W_txt[k * 128 + j] * W_fuse[(256 + j) * 128 + d];
        g_Wc[row * 128 + d] = s;
    } else if (row == 384) {
        float s = b_fuse[d];
        #pragma unroll 4
        for (int j = 0; j < 128; ++j) {
            s += b_img[j] * W_fuse[(128 + j) * 128 + d];
            s += b_txt[j] * W_fuse[(256 + j) * 128 + d];
        }
        g_bc[d] = s;
    } else {
        int l = row - 385;
        const float* pr = pos_emb + (size_t)(23 - l) * 128;
        float s = 0.f;
        #pragma unroll 4
        for (int k = 0; k < 128; ++k) s += pr[k] * w_1[k * 128 + d];
        g_posw[l * 128 + d] = s;
    }
}

// ====================================================================
// Kernel 0b: split emb[1:] into bf16 hi/lo (padded to VPAD rows)
// ====================================================================
__global__ __launch_bounds__(256) void k_split_emb(const float* __restrict__ emb) {
    int idx = blockIdx.x * 256 + threadIdx.x;
    int row = idx >> 7;
    int c = idx & 127;
    float x = (row < VOUT) ? emb[(size_t)(row + 1) * 128 + c] : 0.f;
    __nv_bfloat16 h = __float2bfloat16(x);
    g_embhi[idx] = h;
    g_emblo[idx] = __float2bfloat16(x - __bfloat162float(h));
}

// ====================================================================
// Kernel 1: fused multimodal embedding
// ====================================================================
__global__ __launch_bounds__(256) void k_embed(const int* __restrict__ items,
                                               const float* __restrict__ emb,
                                               const float* __restrict__ img_emb,
                                               const float* __restrict__ txt_emb) {
    __shared__ __align__(16) float Ash[32][132];
    __shared__ int ids[32];
    int rowbase = blockIdx.x * 32;
    int tid = threadIdx.x;
    int d = tid & 127;
    int rh = tid >> 7;
    int r0 = rh * 16;

    if (tid < 32) ids[tid] = items[rowbase + tid];

    float acc[16];
    #pragma unroll
    for (int i = 0; i < 16; ++i) acc[i] = 0.f;

    for (int c = 0; c < 3; ++c) {
        __syncthreads();
        const float* src = (c == 0) ? emb : (c == 1) ? img_emb : txt_emb;
        for (int idx = tid; idx < 32 * 128; idx += 256) {
            int r = idx >> 7, cc = idx & 127;
            Ash[r][cc] = src[(size_t)ids[r] * 128 + cc];
        }
        __syncthreads();
        const float* wc = g_Wc + (size_t)c * 128 * 128 + d;
        #pragma unroll 4
        for (int k = 0; k < 128; k += 4) {
            float w0 = wc[(size_t)(k + 0) * 128];
            float w1 = wc[(size_t)(k + 1) * 128];
            float w2 = wc[(size_t)(k + 2) * 128];
            float w3 = wc[(size_t)(k + 3) * 128];
            #pragma unroll
            for (int rr = 0; rr < 16; ++rr) {
                float4 s4 = *(const float4*)&Ash[r0 + rr][k];
                acc[rr] += s4.x * w0 + s4.y * w1 + s4.z * w2 + s4.w * w3;
            }
        }
    }
    float bias = g_bc[d];
    #pragma unroll
    for (int rr = 0; rr < 16; ++rr)
        g_h[(size_t)(rowbase + r0 + rr) * 128 + d] = acc[rr] + bias;
}

// ====================================================================
// Kernel 2: RGAT layer — warp-per-pair e-computation (conflict-free).
// ====================================================================
__global__ __launch_bounds__(256) void k_rgat(const int* __restrict__ adj,
                                              const float* __restrict__ a_rel) {
    __shared__ __align__(16) float hsh[24][132];
    __shared__ float esh[24][24];
    __shared__ __align__(16) float arel[4][132];
    __shared__ int adjs[576];
    int b = blockIdx.x;
    int tid = threadIdx.x;
    int wid = tid >> 5, lane = tid & 31;

    for (int idx = tid; idx < 24 * 128; idx += 256)
        hsh[idx >> 7][idx & 127] = g_h[(size_t)b * (24 * 128) + idx];
    for (int idx = tid; idx < 4 * 128; idx += 256)
        arel[idx >> 7][idx & 127] = a_rel[idx];
    for (int idx = tid; idx < 576; idx += 256)
        adjs[idx] = adj[b * 576 + idx];
    __syncthreads();

    int d4 = lane * 4;
    for (int p = wid; p < 576; p += 8) {
        int i = p / 24, j = p - i * 24;
        int a = adjs[p];
        float v = NEG_;
        if (a != 0) {
            float4 hi = *(const float4*)&hsh[i][d4];
            float4 hj = *(const float4*)&hsh[j][d4];
            float4 aa = *(const float4*)&arel[a - 1][d4];
            float s = hi.x * hj.x * aa.x + hi.y * hj.y * aa.y
                    + hi.z * hj.z * aa.z + hi.w * hj.w * aa.w;
            #pragma unroll
            for (int off = 16; off > 0; off >>= 1)
                s += __shfl_xor_sync(0xffffffffu, s, off);
            v = (s > 0.f) ? s : ALPHA_ * s;
        }
        if (lane == 0) esh[i][j] = v;
    }
    __syncthreads();

    if (tid < 24) {
        float mx = -INFINITY;
        #pragma unroll
        for (int j = 0; j < 24; ++j) mx = fmaxf(mx, esh[tid][j]);
        float sum = 0.f;
        #pragma unroll
        for (int j = 0; j < 24; ++j) {
            float e = expf(esh[tid][j] - mx);
            esh[tid][j] = e;
            sum += e;
        }
        float inv = 1.f / sum;
        #pragma unroll
        for (int j = 0; j < 24; ++j) esh[tid][j] *= inv;
    }
    __syncthreads();

    for (int idx = tid; idx < 24 * 128; idx += 256) {
        int i = idx >> 7, d2 = idx & 127;
        float s = 0.f;
        #pragma unroll
        for (int j = 0; j < 24; ++j) s += esh[i][j] * hsh[j][d2];
        g_hagg[(size_t)b * (24 * 128) + idx] = s;
    }
}

// ====================================================================
// Kernel 3: session readout (k-outer), writes bf16 hi/lo select
// ====================================================================
__global__ __launch_bounds__(128) void k_readout(const int* __restrict__ alias_,
                                                 const int* __restrict__ mask_,
                                                 const float* __restrict__ w_1,
                                                 const float* __restrict__ w_2,
                                                 const float* __restrict__ glu1_w,
                                                 const float* __restrict__ glu1_b,
                                                 const float* __restrict__ glu2_w) {
    __shared__ __align__(16) float seq[24][128];
    __shared__ __align__(16) float nhsh[24][128];
    __shared__ float hssh[128];
    __shared__ int al[24];
    __shared__ float mk[24];
    __shared__ float betash[24];
    int b = blockIdx.x;
    int d = threadIdx.x;

    if (d < 24) {
        al[d] = alias_[b * 24 + d];
        mk[d] = (float)mask_[b * 24 + d];
    }
    __syncthreads();
    #pragma unroll
    for (int l = 0; l < 24; ++l)
        seq[l][d] = g_hagg[((size_t)b * 24 + al[l]) * 128 + d];
    __syncthreads();

    float msum = 0.f, hs = 0.f;
    #pragma unroll
    for (int l = 0; l < 24; ++l) { msum += mk[l]; hs += mk[l] * seq[l][d]; }
    hs /= fmaxf(msum, 1.f);
    hssh[d] = hs;
    __syncthreads();

    float hsg = 0.f;
    #pragma unroll 4
    for (int k = 0; k < 128; ++k) hsg += hssh[k] * glu2_w[k * 128 + d];

    float acc[24];
    #pragma unroll
    for (int l = 0; l < 24; ++l) acc[l] = g_posw[l * 128 + d];

    #pragma unroll 2
    for (int k = 0; k < 128; k += 4) {
        float w0 = w_1[(128 + k + 0) * 128 + d];
        float w1 = w_1[(128 + k + 1) * 128 + d];
        float w2c = w_1[(128 + k + 2) * 128 + d];
        float w3 = w_1[(128 + k + 3) * 128 + d];
        #pragma unroll
        for (int l = 0; l < 24; ++l) {
            float4 s4 = *(const float4*)&seq[l][k];
            acc[l] += s4.x * w0 + s4.y * w1 + s4.z * w2c + s4.w * w3;
        }
    }
    #pragma unroll
    for (int l = 0; l < 24; ++l) nhsh[l][d] = tanhf(acc[l]);
    __syncthreads();

    float base = glu1_b[d] + hsg;
    #pragma unroll
    for (int l = 0; l < 24; ++l) acc[l] = base;

    #pragma unroll 2
    for (int k = 0; k < 128; k += 4) {
        float w0 = glu1_w[(k + 0) * 128 + d];
        float w1 = glu1_w[(k + 1) * 128 + d];
        float w2c = glu1_w[(k + 2) * 128 + d];
        float w3 = glu1_w[(k + 3) * 128 + d];
        #pragma unroll
        for (int l = 0; l < 24; ++l) {
            float4 s4 = *(const float4*)&nhsh[l][k];
            acc[l] += s4.x * w0 + s4.y * w1 + s4.z * w2c + s4.w * w3;
        }
    }
    float w2d = w_2[d];
    __syncthreads();
    #pragma unroll
    for (int l = 0; l < 24; ++l)
        nhsh[l][d] = (1.f / (1.f + expf(-acc[l]))) * w2d;
    __syncthreads();

    if (d < 24) {
        float s = 0.f;
        #pragma unroll 8
        for (int k = 0; k < 128; k += 4) {
            float4 p4 = *(const float4*)&nhsh[d][k];
            s += p4.x + p4.y + p4.z + p4.w;
        }
        betash[d] = s * mk[d];
    }
    __syncthreads();

    float sel = 0.f;
    #pragma unroll
    for (int l = 0; l < 24; ++l) sel += betash[l] * seq[l][d];

    __nv_bfloat16 h = __float2bfloat16(sel);
    g_selhi[b * 128 + d] = h;
    g_sello[b * 128 + d] = __float2bfloat16(sel - __bfloat162float(h));
}

// ====================================================================
// Kernel 4: scores — pipelined multi-tile bf16 MMA (split-3 terms).
// Grid (GX=18, 8): each CTA owns 128 A rows (resident in smem) and loops
// over n-tiles t = bx, bx+GX, ... with cp.async double-buffered B tiles.
// 512 threads = 16 warps (8m x 2n), warp tile 16m x 64n.
// smem: A hi/lo (2x34KB) + B 2 buffers x hi/lo (4x34KB) = 208896 B.
// ====================================================================
#define PADK 136
#define TILE_ELEMS (128 * PADK)

__device__ __forceinline__ void prefetch_B(__nv_bfloat16* bh, __nv_bfloat16* bl,
                                           int t, int tid) {
    const __nv_bfloat16* sh = g_embhi + (size_t)t * (128 * 128);
    const __nv_bfloat16* sl = g_emblo + (size_t)t * (128 * 128);
    uint32_t bha = smem_u32(bh), bla = smem_u32(bl);
    for (int i = tid; i < 2048; i += 512) {
        int r = i >> 4, c = i & 15;
        uint32_t off = (uint32_t)(r * PADK + c * 8) * 2;
        cpa16(bha + off, sh + r * 128 + c * 8);
        cpa16(bla + off, sl + r * 128 + c * 8);
    }
}

__global__ __launch_bounds__(512) void k_scores_mma(float* __restrict__ out) {
    extern __shared__ __align__(16) __nv_bfloat16 smem[];
    __nv_bfloat16* Ahs = smem;                       // [128][136]
    __nv_bfloat16* Als = Ahs + TILE_ELEMS;
    __nv_bfloat16* Bbuf = Als + TILE_ELEMS;          // 2 x (hi, lo)

    int tid = threadIdx.x;
    int bx = blockIdx.x;
    int m0 = blockIdx.y * 128;

    // prologue: A (resident) + B tile 0 -> group 0; B tile 1 -> group 1
    {
        uint32_t aha = smem_u32(Ahs), ala = smem_u32(Als);
        const __nv_bfloat16* sh = g_selhi + (size_t)m0 * 128;
        const __nv_bfloat16* sl = g_sello + (size_t)m0 * 128;
        for (int i = tid; i < 2048; i += 512) {
            int r = i >> 4, c = i & 15;
            uint32_t off = (uint32_t)(r * PADK + c * 8) * 2;
            cpa16(aha + off, sh + r * 128 + c * 8);
            cpa16(ala + off, sl + r * 128 + c * 8);
        }
        prefetch_B(Bbuf, Bbuf + TILE_ELEMS, bx, tid);
        CP_COMMIT();
        if (bx + GX < NTILES)
            prefetch_B(Bbuf + 2 * TILE_ELEMS, Bbuf + 3 * TILE_ELEMS, bx + GX, tid);
        CP_COMMIT();
    }

    int wid = tid >> 5, lid = tid & 31;
    int wm = (wid & 7) * 16;       // warp m offset
    int wn = (wid >> 3) * 64;      // warp n offset
    uint32_t aH = smem_u32(Ahs), aL = smem_u32(Als);

    int a_row = ((lid >> 3) & 1) * 8 + (lid & 7);
    int a_kof = ((lid >> 4) & 1) * 8;
    int b_n = ((lid >> 4) & 1) * 8 + (lid & 7);
    int b_kof = ((lid >> 3) & 1) * 8;

    int cur = 0;
    for (int t = bx; t < NTILES; t += GX, cur ^= 1) {
        CP_WAIT1();
        __syncthreads();

        __nv_bfloat16* Bh = Bbuf + cur * 2 * TILE_ELEMS;
        __nv_bfloat16* Bl = Bh + TILE_ELEMS;
        uint32_t bH = smem_u32(Bh), bL = smem_u32(Bl);

        float c[8][4];
        #pragma unroll
        for (int ni = 0; ni < 8; ++ni)
            #pragma unroll
            for (int j = 0; j < 4; ++j) c[ni][j] = 0.f;

        #pragma unroll
        for (int kb = 0; kb < 128; kb += 16) {
            uint32_t ah[4], al[4], bh[8][2], bl[8][2];
            uint32_t aoff = (uint32_t)((wm + a_row) * PADK + kb + a_kof) * 2;
            ldsm_x4(ah, aH + aoff);
            ldsm_x4(al, aL + aoff);
            #pragma unroll
            for (int jj = 0; jj < 4; ++jj) {
                uint32_t off = (uint32_t)((wn + jj * 16 + b_n) * PADK + kb + b_kof) * 2;
                uint32_t r[4];
                ldsm_x4(r, bH + off);
                bh[2 * jj][0] = r[0]; bh[2 * jj][1] = r[1];
                bh[2 * jj + 1][0] = r[2]; bh[2 * jj + 1][1] = r[3];
                ldsm_x4(r, bL + off);
                bl[2 * jj][0] = r[0]; bl[2 * jj][1] = r[1];
                bl[2 * jj + 1][0] = r[2]; bl[2 * jj + 1][1] = r[3];
            }
            #pragma unroll
            for (int ni = 0; ni < 8; ++ni) {
                mma_bf16(c[ni], ah, bh[ni]);
                mma_bf16(c[ni], ah, bl[ni]);
                mma_bf16(c[ni], al, bh[ni]);
            }
        }

        // store this tile
        int r0 = m0 + wm + (lid >> 2);
        int c0 = t * 128 + wn + (lid & 3) * 2;
        float* p0 = out + (size_t)r0 * VOUT;
        float* p1 = out + (size_t)(r0 + 8) * VOUT;
        #pragma unroll
        for (int ni = 0; ni < 8; ++ni) {
            int gc = c0 + ni * 8;
            if (gc < VOUT)     p0[gc]     = c[ni][0];
            if (gc + 1 < VOUT) p0[gc + 1] = c[ni][1];
            if (gc < VOUT)     p1[gc]     = c[ni][2];
            if (gc + 1 < VOUT) p1[gc + 1] = c[ni][3];
        }

        __syncthreads();   // all warps done reading buf[cur] before refill
        int tn = t + 2 * GX;
        if (tn < NTILES) {
            __nv_bfloat16* nBh = Bbuf + cur * 2 * TILE_ELEMS;
            prefetch_B(nBh, nBh + TILE_ELEMS, tn, tid);
        }
        CP_COMMIT();       // commit every iteration (possibly empty group)
    }
}

// ====================================================================
// launch
// ====================================================================
extern "C" void kernel_launch(void* const* d_in, const int* in_sizes, int n_in,
                              void* d_out, int out_size) {
    const int*   items   = (const int*)d_in[0];
    const int*   adj     = (const int*)d_in[1];
    const int*   alias_  = (const int*)d_in[2];
    const int*   mask_   = (const int*)d_in[3];
    const float* emb     = (const float*)d_in[4];
    const float* img_emb = (const float*)d_in[5];
    const float* txt_emb = (const float*)d_in[6];
    const float* W_img   = (const float*)d_in[7];
    const float* b_img   = (const float*)d_in[8];
    const float* W_txt   = (const float*)d_in[9];
    const float* b_txt   = (const float*)d_in[10];
    const float* W_fuse  = (const float*)d_in[11];
    const float* b_fuse  = (const float*)d_in[12];
    const float* a_rel   = (const float*)d_in[13];
    const float* pos_emb = (const float*)d_in[14];
    const float* w_1     = (const float*)d_in[15];
    const float* w_2     = (const float*)d_in[16];
    const float* glu1_w  = (const float*)d_in[17];
    const float* glu1_b  = (const float*)d_in[18];
    const float* glu2_w  = (const float*)d_in[19];
    float* out = (float*)d_out;

    k_precompute<<<409, 128>>>(W_img, b_img, W_txt, b_txt, W_fuse, b_fuse, pos_emb, w_1);
    k_split_emb<<<(VPAD * 128) / 256, 256>>>(emb);
    k_embed<<<(B_ * N_) / 32, 256>>>(items, emb, img_emb, txt_emb);
    k_rgat<<<B_, 256>>>(adj, a_rel);
    k_readout<<<B_, 128>>>(alias_, mask_, w_1, w_2, glu1_w, glu1_b, glu2_w);

    int smem_bytes = 6 * TILE_ELEMS * (int)sizeof(__nv_bfloat16);  // 208896
    cudaFuncSetAttribute(k_scores_mma, cudaFuncAttributeMaxDynamicSharedMemorySize, smem_bytes);
    dim3 grid(GX, B_ / 128);   // 18 x 8 = 144 CTAs
    k_scores_mma<<<grid, 512, smem_bytes>>>(out);
}

// round 13
// speedup vs baseline: 2.0624x; 1.0840x over previous
#include <cuda_runtime.h>
#include <cuda_bf16.h>
#include <cuda_fp16.h>
#include <math.h>
#include <stdint.h>

// Problem constants
#define B_   1024
#define N_   24
#define L_   24
#define D_   128
#define V_   40000
#define VOUT 39999           // V-1 output columns
#define VPAD 40064           // 313*128, padded vocab tiles
#define NTILES 313
#define GX 18                // n-tile groups (144 CTAs total, ~1 wave)
#define ALPHA_ 0.2f
#define NEG_ (-9e15f)

// ---------------- scratch (device globals; no runtime allocation) ----------------
static __device__ float g_Wc[384 * 128];
static __device__ float g_bc[128];
static __device__ float g_posw[24 * 128];
static __device__ float g_h[B_ * N_ * D_];
static __device__ float g_hagg[B_ * N_ * D_];
static __device__ __half g_selhi[B_ * D_];      // select fp16 hi
static __device__ __half g_sello[B_ * D_];      // select fp16 lo (residual)
static __device__ __half g_embh[VPAD * D_];     // row v = emb[v+1] in fp16

// ==================== warp-MMA / async-copy helpers (portable PTX, sm_80+) ====================
__device__ __forceinline__ uint32_t smem_u32(const void* p) {
    uint32_t a;
    asm("{ .reg .u64 t; cvta.to.shared.u64 t, %1; cvt.u32.u64 %0, t; }" : "=r"(a) : "l"(p));
    return a;
}
__device__ __forceinline__ void ldsm_x4(uint32_t* r, uint32_t addr) {
    asm volatile("ldmatrix.sync.aligned.m8n8.x4.shared.b16 {%0,%1,%2,%3}, [%4];"
                 : "=r"(r[0]), "=r"(r[1]), "=r"(r[2]), "=r"(r[3]) : "r"(addr));
}
__device__ __forceinline__ void mma_fp16(float* c, const uint32_t* a, const uint32_t* b) {
    asm volatile("mma.sync.aligned.m16n8k16.row.col.f32.f16.f16.f32 "
                 "{%0,%1,%2,%3}, {%4,%5,%6,%7}, {%8,%9}, {%0,%1,%2,%3};"
                 : "+f"(c[0]), "+f"(c[1]), "+f"(c[2]), "+f"(c[3])
                 : "r"(a[0]), "r"(a[1]), "r"(a[2]), "r"(a[3]), "r"(b[0]), "r"(b[1]));
}
__device__ __forceinline__ void cpa16(uint32_t sa, const void* g) {
    asm volatile("{\n\t.reg .u64 gg;\n\tcvta.to.global.u64 gg, %1;\n\t"
                 "cp.async.cg.shared.global [%0], [gg], 16;\n\t}"
                 :: "r"(sa), "l"(g) : "memory");
}
#define CP_COMMIT() asm volatile("cp.async.commit_group;" ::: "memory")
#define CP_WAIT1()  asm volatile("cp.async.wait_group 1;" ::: "memory")

// ====================================================================
// Kernel 0: fold weights + pos projection
// ====================================================================
__global__ void k_precompute(const float* __restrict__ W_img, const float* __restrict__ b_img,
                             const float* __restrict__ W_txt, const float* __restrict__ b_txt,
                             const float* __restrict__ W_fuse, const float* __restrict__ b_fuse,
                             const float* __restrict__ pos_emb, const float* __restrict__ w_1) {
    int row = blockIdx.x;
    int d = threadIdx.x;
    if (row < 128) {
        g_Wc[row * 128 + d] = W_fuse[row * 128 + d];
    } else if (row < 256) {
        int k = row - 128;
        float s = 0.f;
        #pragma unroll 4
        for (int j = 0; j < 128; ++j) s += W_img[k * 128 + j] * W_fuse[(128 + j) * 128 + d];
        g_Wc[row * 128 + d] = s;
    } else if (row < 384) {
        int k = row - 256;
        float s = 0.f;
        #pragma unroll 4
        for (int j = 0; j < 128; ++j) s += W_txt[k * 128 + j] * W_fuse[(256 + j) * 128 + d];
        g_Wc[row * 128 + d] = s;
    } else if (row == 384) {
        float s = b_fuse[d];
        #pragma unroll 4
        for (int j = 0; j < 128; ++j) {
            s += b_img[j] * W_fuse[(128 + j) * 128 + d];
            s += b_txt[j] * W_fuse[(256 + j) * 128 + d];
        }
        g_bc[d] = s;
    } else {
        int l = row - 385;
        const float* pr = pos_emb + (size_t)(23 - l) * 128;
        float s = 0.f;
        #pragma unroll 4
        for (int k = 0; k < 128; ++k) s += pr[k] * w_1[k * 128 + d];
        g_posw[l * 128 + d] = s;
    }
}

// ====================================================================
// Kernel 0b: convert emb[1:] to fp16 (padded to VPAD rows)
// ====================================================================
__global__ __launch_bounds__(256) void k_split_emb(const float* __restrict__ emb) {
    int idx = blockIdx.x * 256 + threadIdx.x;
    int row = idx >> 7;
    int c = idx & 127;
    float x = (row < VOUT) ? emb[(size_t)(row + 1) * 128 + c] : 0.f;
    g_embh[idx] = __float2half(x);
}

// ====================================================================
// Kernel 1: fused multimodal embedding
// ====================================================================
__global__ __launch_bounds__(256) void k_embed(const int* __restrict__ items,
                                               const float* __restrict__ emb,
                                               const float* __restrict__ img_emb,
                                               const float* __restrict__ txt_emb) {
    __shared__ __align__(16) float Ash[32][132];
    __shared__ int ids[32];
    int rowbase = blockIdx.x * 32;
    int tid = threadIdx.x;
    int d = tid & 127;
    int rh = tid >> 7;
    int r0 = rh * 16;

    if (tid < 32) ids[tid] = items[rowbase + tid];

    float acc[16];
    #pragma unroll
    for (int i = 0; i < 16; ++i) acc[i] = 0.f;

    for (int c = 0; c < 3; ++c) {
        __syncthreads();
        const float* src = (c == 0) ? emb : (c == 1) ? img_emb : txt_emb;
        for (int idx = tid; idx < 32 * 128; idx += 256) {
            int r = idx >> 7, cc = idx & 127;
            Ash[r][cc] = src[(size_t)ids[r] * 128 + cc];
        }
        __syncthreads();
        const float* wc = g_Wc + (size_t)c * 128 * 128 + d;
        #pragma unroll 4
        for (int k = 0; k < 128; k += 4) {
            float w0 = wc[(size_t)(k + 0) * 128];
            float w1 = wc[(size_t)(k + 1) * 128];
            float w2 = wc[(size_t)(k + 2) * 128];
            float w3 = wc[(size_t)(k + 3) * 128];
            #pragma unroll
            for (int rr = 0; rr < 16; ++rr) {
                float4 s4 = *(const float4*)&Ash[r0 + rr][k];
                acc[rr] += s4.x * w0 + s4.y * w1 + s4.z * w2 + s4.w * w3;
            }
        }
    }
    float bias = g_bc[d];
    #pragma unroll
    for (int rr = 0; rr < 16; ++rr)
        g_h[(size_t)(rowbase + r0 + rr) * 128 + d] = acc[rr] + bias;
}

// ====================================================================
// Kernel 2: RGAT layer — 8-lanes-per-pair (4 pairs/warp, 3 shfl steps).
// ====================================================================
__global__ __launch_bounds__(256) void k_rgat(const int* __restrict__ adj,
                                              const float* __restrict__ a_rel) {
    __shared__ __align__(16) float hsh[24][132];
    __shared__ float esh[24][24];
    __shared__ __align__(16) float arel[4][132];
    __shared__ int adjs[576];
    int b = blockIdx.x;
    int tid = threadIdx.x;
    int wid = tid >> 5, lane = tid & 31;

    for (int idx = tid; idx < 24 * 128; idx += 256)
        hsh[idx >> 7][idx & 127] = g_h[(size_t)b * (24 * 128) + idx];
    for (int idx = tid; idx < 4 * 128; idx += 256)
        arel[idx >> 7][idx & 127] = a_rel[idx];
    for (int idx = tid; idx < 576; idx += 256)
        adjs[idx] = adj[b * 576 + idx];
    __syncthreads();

    // 8-lane groups: group g of warp handles pair q; lane s covers dims s*4+32c
    int s_ = lane & 7, g_ = lane >> 3;
    for (int q = wid * 4 + g_; q < 576; q += 32) {     // 18 iterations exactly
        int i = q / 24, j = q - i * 24;
        int a = adjs[q];                               // uniform within 8-lane group
        const float* ar = arel[(a > 0) ? (a - 1) : 0];
        float sum = 0.f;
        #pragma unroll
        for (int c = 0; c < 4; ++c) {
            int d0 = s_ * 4 + c * 32;
            float4 hi = *(const float4*)&hsh[i][d0];
            float4 hj = *(const float4*)&hsh[j][d0];
            float4 aa = *(const float4*)&ar[d0];
            sum += hi.x * hj.x * aa.x + hi.y * hj.y * aa.y
                 + hi.z * hj.z * aa.z + hi.w * hj.w * aa.w;
        }
        sum += __shfl_xor_sync(0xffffffffu, sum, 1);
        sum += __shfl_xor_sync(0xffffffffu, sum, 2);
        sum += __shfl_xor_sync(0xffffffffu, sum, 4);
        float v = (a == 0) ? NEG_ : ((sum > 0.f) ? sum : ALPHA_ * sum);
        if (s_ == 0) esh[i][j] = v;
    }
    __syncthreads();

    if (tid < 24) {
        float mx = -INFINITY;
        #pragma unroll
        for (int j = 0; j < 24; ++j) mx = fmaxf(mx, esh[tid][j]);
        float sum = 0.f;
        #pragma unroll
        for (int j = 0; j < 24; ++j) {
            float e = expf(esh[tid][j] - mx);
            esh[tid][j] = e;
            sum += e;
        }
        float inv = 1.f / sum;
        #pragma unroll
        for (int j = 0; j < 24; ++j) esh[tid][j] *= inv;
    }
    __syncthreads();

    for (int idx = tid; idx < 24 * 128; idx += 256) {
        int i = idx >> 7, d2 = idx & 127;
        float s = 0.f;
        #pragma unroll
        for (int j = 0; j < 24; ++j) s += esh[i][j] * hsh[j][d2];
        g_hagg[(size_t)b * (24 * 128) + idx] = s;
    }
}

// ====================================================================
// Kernel 3: session readout (k-outer), writes fp16 hi/lo select
// ====================================================================
__global__ __launch_bounds__(128) void k_readout(const int* __restrict__ alias_,
                                                 const int* __restrict__ mask_,
                                                 const float* __restrict__ w_1,
                                                 const float* __restrict__ w_2,
                                                 const float* __restrict__ glu1_w,
                                                 const float* __restrict__ glu1_b,
                                                 const float* __restrict__ glu2_w) {
    __shared__ __align__(16) float seq[24][128];
    __shared__ __align__(16) float nhsh[24][128];
    __shared__ float hssh[128];
    __shared__ int al[24];
    __shared__ float mk[24];
    __shared__ float betash[24];
    int b = blockIdx.x;
    int d = threadIdx.x;

    if (d < 24) {
        al[d] = alias_[b * 24 + d];
        mk[d] = (float)mask_[b * 24 + d];
    }
    __syncthreads();
    #pragma unroll
    for (int l = 0; l < 24; ++l)
        seq[l][d] = g_hagg[((size_t)b * 24 + al[l]) * 128 + d];
    __syncthreads();

    float msum = 0.f, hs = 0.f;
    #pragma unroll
    for (int l = 0; l < 24; ++l) { msum += mk[l]; hs += mk[l] * seq[l][d]; }
    hs /= fmaxf(msum, 1.f);
    hssh[d] = hs;
    __syncthreads();

    float hsg = 0.f;
    #pragma unroll 4
    for (int k = 0; k < 128; ++k) hsg += hssh[k] * glu2_w[k * 128 + d];

    float acc[24];
    #pragma unroll
    for (int l = 0; l < 24; ++l) acc[l] = g_posw[l * 128 + d];

    #pragma unroll 2
    for (int k = 0; k < 128; k += 4) {
        float w0 = w_1[(128 + k + 0) * 128 + d];
        float w1 = w_1[(128 + k + 1) * 128 + d];
        float w2c = w_1[(128 + k + 2) * 128 + d];
        float w3 = w_1[(128 + k + 3) * 128 + d];
        #pragma unroll
        for (int l = 0; l < 24; ++l) {
            float4 s4 = *(const float4*)&seq[l][k];
            acc[l] += s4.x * w0 + s4.y * w1 + s4.z * w2c + s4.w * w3;
        }
    }
    #pragma unroll
    for (int l = 0; l < 24; ++l) nhsh[l][d] = tanhf(acc[l]);
    __syncthreads();

    float base = glu1_b[d] + hsg;
    #pragma unroll
    for (int l = 0; l < 24; ++l) acc[l] = base;

    #pragma unroll 2
    for (int k = 0; k < 128; k += 4) {
        float w0 = glu1_w[(k + 0) * 128 + d];
        float w1 = glu1_w[(k + 1) * 128 + d];
        float w2c = glu1_w[(k + 2) * 128 + d];
        float w3 = glu1_w[(k + 3) * 128 + d];
        #pragma unroll
        for (int l = 0; l < 24; ++l) {
            float4 s4 = *(const float4*)&nhsh[l][k];
            acc[l] += s4.x * w0 + s4.y * w1 + s4.z * w2c + s4.w * w3;
        }
    }
    float w2d = w_2[d];
    __syncthreads();
    #pragma unroll
    for (int l = 0; l < 24; ++l)
        nhsh[l][d] = (1.f / (1.f + expf(-acc[l]))) * w2d;
    __syncthreads();

    if (d < 24) {
        float s = 0.f;
        #pragma unroll 8
        for (int k = 0; k < 128; k += 4) {
            float4 p4 = *(const float4*)&nhsh[d][k];
            s += p4.x + p4.y + p4.z + p4.w;
        }
        betash[d] = s * mk[d];
    }
    __syncthreads();

    float sel = 0.f;
    #pragma unroll
    for (int l = 0; l < 24; ++l) sel += betash[l] * seq[l][d];

    __half h = __float2half(sel);
    g_selhi[b * 128 + d] = h;
    g_sello[b * 128 + d] = __float2half(sel - __half2float(h));
}

// ====================================================================
// Kernel 4: scores — pipelined fp16 MMA, 2 terms: (Ah + Al) * Bh.
// Grid (GX=18, 8): CTA owns 128 A rows resident; loops n-tiles with
// cp.async double-buffered single-fp16 B tiles.
// 512 threads = 16 warps (8m x 2n), warp tile 16m x 64n.
// smem: A hi/lo (2x34KB) + B 2 stages (2x34KB) = 139264 B.
// ====================================================================
#define PADK 136
#define TILE_ELEMS (128 * PADK)

__device__ __forceinline__ void prefetch_B(__half* bh, int t, int tid) {
    const __half* sh = g_embh + (size_t)t * (128 * 128);
    uint32_t bha = smem_u32(bh);
    for (int i = tid; i < 2048; i += 512) {
        int r = i >> 4, c = i & 15;
        cpa16(bha + (uint32_t)(r * PADK + c * 8) * 2, sh + r * 128 + c * 8);
    }
}

__global__ __launch_bounds__(512) void k_scores_mma(float* __restrict__ out) {
    extern __shared__ __align__(16) __half smem[];
    __half* Ahs = smem;                       // [128][136]
    __half* Als = Ahs + TILE_ELEMS;
    __half* Bbuf = Als + TILE_ELEMS;          // 2 stages

    int tid = threadIdx.x;
    int bx = blockIdx.x;
    int m0 = blockIdx.y * 128;

    // prologue: A (resident) + B tile 0 -> group 0; B tile 1 -> group 1
    {
        uint32_t aha = smem_u32(Ahs), ala = smem_u32(Als);
        const __half* sh = g_selhi + (size_t)m0 * 128;
        const __half* sl = g_sello + (size_t)m0 * 128;
        for (int i = tid; i < 2048; i += 512) {
            int r = i >> 4, c = i & 15;
            uint32_t off = (uint32_t)(r * PADK + c * 8) * 2;
            cpa16(aha + off, sh + r * 128 + c * 8);
            cpa16(ala + off, sl + r * 128 + c * 8);
        }
        prefetch_B(Bbuf, bx, tid);
        CP_COMMIT();
        if (bx + GX < NTILES)
            prefetch_B(Bbuf + TILE_ELEMS, bx + GX, tid);
        CP_COMMIT();
    }

    int wid = tid >> 5, lid = tid & 31;
    int wm = (wid & 7) * 16;       // warp m offset
    int wn = (wid >> 3) * 64;      // warp n offset
    uint32_t aH = smem_u32(Ahs), aL = smem_u32(Als);

    int a_row = ((lid >> 3) & 1) * 8 + (lid & 7);
    int a_kof = ((lid >> 4) & 1) * 8;
    int b_n = ((lid >> 4) & 1) * 8 + (lid & 7);
    int b_kof = ((lid >> 3) & 1) * 8;

    int cur = 0;
    for (int t = bx; t < NTILES; t += GX, cur ^= 1) {
        CP_WAIT1();
        __syncthreads();

        uint32_t bH = smem_u32(Bbuf + cur * TILE_ELEMS);

        float c[8][4];
        #pragma unroll
        for (int ni = 0; ni < 8; ++ni)
            #pragma unroll
            for (int j = 0; j < 4; ++j) c[ni][j] = 0.f;

        #pragma unroll
        for (int kb = 0; kb < 128; kb += 16) {
            uint32_t ah[4], al[4], bh[8][2];
            uint32_t aoff = (uint32_t)((wm + a_row) * PADK + kb + a_kof) * 2;
            ldsm_x4(ah, aH + aoff);
            ldsm_x4(al, aL + aoff);
            #pragma unroll
            for (int jj = 0; jj < 4; ++jj) {
                uint32_t off = (uint32_t)((wn + jj * 16 + b_n) * PADK + kb + b_kof) * 2;
                uint32_t r[4];
                ldsm_x4(r, bH + off);
                bh[2 * jj][0] = r[0]; bh[2 * jj][1] = r[1];
                bh[2 * jj + 1][0] = r[2]; bh[2 * jj + 1][1] = r[3];
            }
            #pragma unroll
            for (int ni = 0; ni < 8; ++ni) {
                mma_fp16(c[ni], ah, bh[ni]);
                mma_fp16(c[ni], al, bh[ni]);
            }
        }

        // store this tile
        int r0 = m0 + wm + (lid >> 2);
        int c0 = t * 128 + wn + (lid & 3) * 2;
        float* p0 = out + (size_t)r0 * VOUT;
        float* p1 = out + (size_t)(r0 + 8) * VOUT;
        #pragma unroll
        for (int ni = 0; ni < 8; ++ni) {
            int gc = c0 + ni * 8;
            if (gc < VOUT)     p0[gc]     = c[ni][0];
            if (gc + 1 < VOUT) p0[gc + 1] = c[ni][1];
            if (gc < VOUT)     p1[gc]     = c[ni][2];
            if (gc + 1 < VOUT) p1[gc + 1] = c[ni][3];
        }

        __syncthreads();   // all warps done reading buf[cur] before refill
        int tn = t + 2 * GX;
        if (tn < NTILES)
            prefetch_B(Bbuf + cur * TILE_ELEMS, tn, tid);
        CP_COMMIT();       // commit every iteration (possibly empty group)
    }
}

// ====================================================================
// launch
// ====================================================================
extern "C" void kernel_launch(void* const* d_in, const int* in_sizes, int n_in,
                              void* d_out, int out_size) {
    const int*   items   = (const int*)d_in[0];
    const int*   adj     = (const int*)d_in[1];
    const int*   alias_  = (const int*)d_in[2];
    const int*   mask_   = (const int*)d_in[3];
    const float* emb     = (const float*)d_in[4];
    const float* img_emb = (const float*)d_in[5];
    const float* txt_emb = (const float*)d_in[6];
    const float* W_img   = (const float*)d_in[7];
    const float* b_img   = (const float*)d_in[8];
    const float* W_txt   = (const float*)d_in[9];
    const float* b_txt   = (const float*)d_in[10];
    const float* W_fuse  = (const float*)d_in[11];
    const float* b_fuse  = (const float*)d_in[12];
    const float* a_rel   = (const float*)d_in[13];
    const float* pos_emb = (const float*)d_in[14];
    const float* w_1     = (const float*)d_in[15];
    const float* w_2     = (const float*)d_in[16];
    const float* glu1_w  = (const float*)d_in[17];
    const float* glu1_b  = (const float*)d_in[18];
    const float* glu2_w  = (const float*)d_in[19];
    float* out = (float*)d_out;

    k_precompute<<<409, 128>>>(W_img, b_img, W_txt, b_txt, W_fuse, b_fuse, pos_emb, w_1);
    k_split_emb<<<(VPAD * 128) / 256, 256>>>(emb);
    k_embed<<<(B_ * N_) / 32, 256>>>(items, emb, img_emb, txt_emb);
    k_rgat<<<B_, 256>>>(adj, a_rel);
    k_readout<<<B_, 128>>>(alias_, mask_, w_1, w_2, glu1_w, glu1_b, glu2_w);

    int smem_bytes = 4 * TILE_ELEMS * (int)sizeof(__half);  // 139264
    cudaFuncSetAttribute(k_scores_mma, cudaFuncAttributeMaxDynamicSharedMemorySize, smem_bytes);
    dim3 grid(GX, B_ / 128);   // 18 x 8 = 144 CTAs
    k_scores_mma<<<grid, 512, smem_bytes>>>(out);
}